// round 14
// baseline (speedup 1.0000x reference)
#include <cuda_runtime.h>
#include <cuda_bf16.h>
#include <math.h>

// Problem dims
// B=4, T=4096 -> M=16384 rows; H=2048; D=256; NH=4; K=32; NB=65536; NG=16; NK=NH*K=128

// ---------------- device scratch (no allocations allowed) ----------------
__device__ float g_partial[64 * 2048];
__device__ float g_meanq[2048];
__device__ float g_q1024[1024];
__device__ float g_scores[65536];
__device__ float g_candV[8192];
__device__ int   g_candI[8192];
__device__ float g_cand2V[512];
__device__ int   g_cand2I[512];
__device__ float g_keys[32 * 256];
__device__ float g_vals[32 * 256];
__device__ float g_bias[32];
__device__ float g_temp[4];

// bf16 hi/lo split planes
__device__ __nv_bfloat16 g_hid_hi[16384 * 2048];
__device__ __nv_bfloat16 g_hid_lo[16384 * 2048];
__device__ __nv_bfloat16 g_W1Thi[128 * 2048];   // [nk][h]
__device__ __nv_bfloat16 g_W1Tlo[128 * 2048];
__device__ __nv_bfloat16 g_W2Thi[2048 * 128];   // [j][nk]
__device__ __nv_bfloat16 g_W2Tlo[2048 * 128];

// ---------------- PTX helpers ----------------
__device__ __forceinline__ unsigned smem_u32(const void* p) {
    return (unsigned)__cvta_generic_to_shared(p);
}
__device__ __forceinline__ void cp16(unsigned dst, const void* src) {
    asm volatile("cp.async.cg.shared.global [%0], [%1], 16;" :: "r"(dst), "l"(src));
}
__device__ __forceinline__ void cp_commit() { asm volatile("cp.async.commit_group;"); }
__device__ __forceinline__ void ldsm4(unsigned* r, unsigned addr) {
    asm volatile("ldmatrix.sync.aligned.m8n8.x4.shared.b16 {%0,%1,%2,%3}, [%4];"
        : "=r"(r[0]), "=r"(r[1]), "=r"(r[2]), "=r"(r[3]) : "r"(addr));
}
// b0 = k[0:8] half, b1 = k[8:16] half of the SAME n8 subtile (non-contiguous regs)
__device__ __forceinline__ void mma16816(float* c, const unsigned* a, unsigned b0, unsigned b1) {
    asm volatile("mma.sync.aligned.m16n8k16.row.col.f32.bf16.bf16.f32 "
        "{%0,%1,%2,%3}, {%4,%5,%6,%7}, {%8,%9}, {%0,%1,%2,%3};"
        : "+f"(c[0]), "+f"(c[1]), "+f"(c[2]), "+f"(c[3])
        : "r"(a[0]), "r"(a[1]), "r"(a[2]), "r"(a[3]), "r"(b0), "r"(b1));
}
__device__ __forceinline__ void split_bf16(float x, __nv_bfloat16& h, __nv_bfloat16& l) {
    h = __float2bfloat16(x);
    l = __float2bfloat16(x - __bfloat162float(h));
}
// pack float4 -> 4 bf16 (8B) for hi and lo planes
__device__ __forceinline__ void split_pack4(float4 f, uint2& hi, uint2& lo) {
    __nv_bfloat16 hx, lx, hy, ly, hz, lz, hw, lw;
    split_bf16(f.x, hx, lx); split_bf16(f.y, hy, ly);
    split_bf16(f.z, hz, lz); split_bf16(f.w, hw, lw);
    hi.x = (unsigned)__bfloat16_as_ushort(hx) | ((unsigned)__bfloat16_as_ushort(hy) << 16);
    hi.y = (unsigned)__bfloat16_as_ushort(hz) | ((unsigned)__bfloat16_as_ushort(hw) << 16);
    lo.x = (unsigned)__bfloat16_as_ushort(lx) | ((unsigned)__bfloat16_as_ushort(ly) << 16);
    lo.y = (unsigned)__bfloat16_as_ushort(lz) | ((unsigned)__bfloat16_as_ushort(lw) << 16);
}

// ---------------- 1) column sums + hi/lo split of hidden (float4 per thread) ----------------
// grid (64 row-chunks, 2 col-chunks of 1024), block 256. Per-column sum order
// identical to scalar version -> bitwise-identical g_meanq.
__global__ void k_convsum(const float* __restrict__ hidden) {
    int col = blockIdx.y * 1024 + threadIdx.x * 4;
    int r0  = blockIdx.x * 256;
    float4 s = make_float4(0.f, 0.f, 0.f, 0.f);
#pragma unroll 4
    for (int r = 0; r < 256; r++) {
        size_t idx = (size_t)(r0 + r) * 2048 + col;
        float4 x = *reinterpret_cast<const float4*>(hidden + idx);
        s.x += x.x; s.y += x.y; s.z += x.z; s.w += x.w;
        uint2 hi, lo;
        split_pack4(x, hi, lo);
        *reinterpret_cast<uint2*>(g_hid_hi + idx) = hi;
        *reinterpret_cast<uint2*>(g_hid_lo + idx) = lo;
    }
    *reinterpret_cast<float4*>(&g_partial[blockIdx.x * 2048 + col]) = s;
}

__global__ void k_mean() {
    int col = blockIdx.x * 256 + threadIdx.x;
    float s = 0.f;
#pragma unroll
    for (int r = 0; r < 64; r++) s += g_partial[r * 2048 + col];
    g_meanq[col] = s * (1.0f / 16384.0f);
}

// ---------------- 2) q1024 = Wq @ mean_query ----------------
__global__ void k_q1024(const float* __restrict__ Wq) {
    int row  = (blockIdx.x << 3) + (threadIdx.x >> 5);
    int lane = threadIdx.x & 31;
    const float* wp = Wq + (size_t)row * 2048;
    float s = 0.f;
#pragma unroll 8
    for (int j = 0; j < 64; j++) s += wp[j * 32 + lane] * g_meanq[j * 32 + lane];
#pragma unroll
    for (int off = 16; off > 0; off >>= 1) s += __shfl_xor_sync(0xffffffffu, s, off);
    if (lane == 0) g_q1024[row] = s;
}

// ---------------- 3) rough scores ----------------
__global__ void k_rough(const float* __restrict__ beliefs, const int* __restrict__ mask) {
    __shared__ float rqS[256];
    int t = threadIdx.x;
    rqS[t] = 0.25f * (g_q1024[t] + g_q1024[256 + t] + g_q1024[512 + t] + g_q1024[768 + t]);
    __syncthreads();
    int w    = (blockIdx.x << 3) + (t >> 5);
    int lane = t & 31;
    const float* bp = beliefs + (size_t)w * 256;
    float dot = 0.f, ss = 0.f;
#pragma unroll
    for (int j = 0; j < 8; j++) {
        float v = bp[j * 32 + lane];
        dot += v * rqS[j * 32 + lane];
        ss  += v * v;
    }
#pragma unroll
    for (int off = 16; off > 0; off >>= 1) {
        dot += __shfl_xor_sync(0xffffffffu, dot, off);
        ss  += __shfl_xor_sync(0xffffffffu, ss, off);
    }
    if (lane == 0) {
        float score = dot / fmaxf(sqrtf(ss), 1e-8f);
        g_scores[w] = (mask[w] != 0) ? score : -1e30f;
    }
}

// ---------------- 4) top-32 via HIERARCHICAL rank counting ----------------
__global__ void k_topA() {
    __shared__ __align__(16) float sv[256];
    int t = threadIdx.x;
    float v = g_scores[blockIdx.x * 256 + t];
    sv[t] = v;
    __syncthreads();
    int rank = 0;
#pragma unroll 16
    for (int j4 = 0; j4 < 64; j4++) {
        float4 f = *reinterpret_cast<const float4*>(&sv[j4 * 4]);
        int j = j4 * 4;
        rank += (f.x > v) || (f.x == v && (j + 0) < t);
        rank += (f.y > v) || (f.y == v && (j + 1) < t);
        rank += (f.z > v) || (f.z == v && (j + 2) < t);
        rank += (f.w > v) || (f.w == v && (j + 3) < t);
    }
    if (rank < 32) {
        g_candV[blockIdx.x * 32 + rank] = v;
        g_candI[blockIdx.x * 32 + rank] = blockIdx.x * 256 + t;
    }
}

__global__ void k_topB1() {
    __shared__ __align__(16) float sv[512];
    int t = threadIdx.x;
    int base = blockIdx.x * 512;
    float v = g_candV[base + t];
    sv[t] = v;
    __syncthreads();
    int rank = 0;
#pragma unroll 16
    for (int j4 = 0; j4 < 128; j4++) {
        float4 f = *reinterpret_cast<const float4*>(&sv[j4 * 4]);
        int j = j4 * 4;
        rank += (f.x > v) || (f.x == v && (j + 0) < t);
        rank += (f.y > v) || (f.y == v && (j + 1) < t);
        rank += (f.z > v) || (f.z == v && (j + 2) < t);
        rank += (f.w > v) || (f.w == v && (j + 3) < t);
    }
    if (rank < 32) {
        g_cand2V[blockIdx.x * 32 + rank] = v;
        g_cand2I[blockIdx.x * 32 + rank] = g_candI[base + t];
    }
}

// ---------------- 5) topB2 (final rank) + keys/values/bias/temp, fused ----------------
__global__ void k_topB2prep(const float* __restrict__ beliefs,
                            const float* __restrict__ ge,
                            const float* __restrict__ gp,
                            const float* __restrict__ lt) {
    __shared__ __align__(16) float sv[512];
    __shared__ int topkS[32];
    __shared__ float gA[16][256];
    __shared__ float gpS[16];
    int t = threadIdx.x, w = t >> 5, lane = t & 31;

    if (t < 512) sv[t] = g_cand2V[t];
    if (t < 4)  g_temp[t] = fmaxf(expf(lt[t]), 0.1f);
    if (t < 16) gpS[t] = gp[t];
    __syncthreads();

    if (t < 512) {
        float v = sv[t];
        int rank = 0;
#pragma unroll 16
        for (int j4 = 0; j4 < 128; j4++) {
            float4 f = *reinterpret_cast<const float4*>(&sv[j4 * 4]);
            int j = j4 * 4;
            rank += (f.x > v) || (f.x == v && (j + 0) < t);
            rank += (f.y > v) || (f.y == v && (j + 1) < t);
            rank += (f.z > v) || (f.z == v && (j + 2) < t);
            rank += (f.w > v) || (f.w == v && (j + 3) < t);
        }
        if (rank < 32) topkS[rank] = g_cand2I[t];
    }
    __syncthreads();

    int idx = topkS[w];
    float v[8], kreg[8];
    float ss = 0.f;
#pragma unroll
    for (int j = 0; j < 8; j++) {
        v[j] = beliefs[(size_t)idx * 256 + j * 32 + lane];
        ss += v[j] * v[j];
    }
#pragma unroll
    for (int off = 16; off > 0; off >>= 1) ss += __shfl_xor_sync(0xffffffffu, ss, off);
    float inv = 1.0f / fmaxf(sqrtf(ss), 1e-8f);
#pragma unroll
    for (int j = 0; j < 8; j++) {
        kreg[j] = v[j] * inv;
        g_keys[w * 256 + j * 32 + lane] = kreg[j];
        g_vals[w * 256 + j * 32 + lane] = v[j];
    }
    if (w < 16) {
        float gv[8]; float gs = 0.f;
#pragma unroll
        for (int j = 0; j < 8; j++) {
            gv[j] = ge[w * 256 + j * 32 + lane];
            gs += gv[j] * gv[j];
        }
#pragma unroll
        for (int off = 16; off > 0; off >>= 1) gs += __shfl_xor_sync(0xffffffffu, gs, off);
        float gi = 1.0f / fmaxf(sqrtf(gs), 1e-8f);
#pragma unroll
        for (int j = 0; j < 8; j++) gA[w][j * 32 + lane] = gv[j] * gi;
    }
    __syncthreads();
    float best = -INFINITY;
#pragma unroll
    for (int g = 0; g < 16; g++) {
        float d = 0.f;
#pragma unroll
        for (int j = 0; j < 8; j++) d += kreg[j] * gA[g][j * 32 + lane];
#pragma unroll
        for (int off = 16; off > 0; off >>= 1) d += __shfl_xor_sync(0xffffffffu, d, off);
        best = fmaxf(best, d * gpS[g]);
    }
    if (lane == 0) g_bias[w] = best;
}

// ---------------- 6) W1T[nk][h], bf16 hi/lo ----------------
__global__ void __launch_bounds__(256) k_W1(const float* __restrict__ Wq) {
    __shared__ float keysS[32 * 256];
    __shared__ float aS[8 * 64];
    int t = threadIdx.x;
    int h0 = blockIdx.x * 64;
    int head = blockIdx.y;
#pragma unroll
    for (int i = 0; i < 32; i++) keysS[t + i * 256] = g_keys[t + i * 256];
    float acc[8];
#pragma unroll
    for (int j = 0; j < 8; j++) acc[j] = 0.f;
    int k4 = t >> 6, hl = t & 63;
    for (int dc = 0; dc < 32; dc++) {
        __syncthreads();
#pragma unroll
        for (int i = 0; i < 2; i++) {
            int e = t + i * 256;
            int dd = e >> 6, hh = e & 63;
            aS[dd * 64 + hh] = Wq[(size_t)(head * 256 + dc * 8 + dd) * 2048 + h0 + hh];
        }
        __syncthreads();
#pragma unroll
        for (int dd = 0; dd < 8; dd++) {
            float a = aS[dd * 64 + hl];
            int dg = dc * 8 + dd;
#pragma unroll
            for (int j = 0; j < 8; j++) acc[j] += a * keysS[(k4 * 8 + j) * 256 + dg];
        }
    }
    float scale = g_temp[head] * 0.0625f;
#pragma unroll
    for (int j = 0; j < 8; j++) {
        float v = acc[j] * scale;
        __nv_bfloat16 h, l;
        split_bf16(v, h, l);
        size_t o = (size_t)(head * 32 + k4 * 8 + j) * 2048 + h0 + hl;
        g_W1Thi[o] = h;
        g_W1Tlo[o] = l;
    }
}

// ---------------- 7) W2T[j][nk], bf16 hi/lo ----------------
__global__ void __launch_bounds__(128) k_W2(const float* __restrict__ Wo) {
    __shared__ float woS[1024];
    __shared__ float valT[256 * 33];
    int t = threadIdx.x;
    int j = blockIdx.x;
#pragma unroll
    for (int i = 0; i < 8; i++) woS[t + i * 128] = Wo[(size_t)j * 1024 + t + i * 128];
#pragma unroll
    for (int i = 0; i < 64; i++) {
        int e = t + i * 128;
        int k = e >> 8, d = e & 255;
        valT[d * 33 + k] = g_vals[e];
    }
    __syncthreads();
    int n = t >> 5, k = t & 31;
    float acc = 0.f;
#pragma unroll 8
    for (int d = 0; d < 256; d++) acc += valT[d * 33 + k] * woS[n * 256 + d];
    __nv_bfloat16 h, l;
    split_bf16(acc, h, l);
    g_W2Thi[(size_t)j * 128 + t] = h;
    g_W2Tlo[(size_t)j * 128 + t] = l;
}

// ---------------- 8) FUSED (verbatim R10): attn in SMEM, then out = attn@W2 ----------------
static constexpr int ATTN_OFF  = 0;
static constexpr int PIPE_OFF  = 69632;
static constexpr int W2ST_OFF  = 69632;
static constexpr int FUSED_SMEM = 208896;

__global__ void __launch_bounds__(256) k_fused(float* __restrict__ out) {
    extern __shared__ __align__(16) char smraw[];
    __nv_bfloat16* attnS = reinterpret_cast<__nv_bfloat16*>(smraw + ATTN_OFF);
    __nv_bfloat16* sA = reinterpret_cast<__nv_bfloat16*>(smraw + PIPE_OFF);
    __nv_bfloat16* sB = sA + 20480;

    int t = threadIdx.x;
    int lane = t & 31, w = t >> 5;
    int wm = w & 3, wn = w >> 2;
    int m0 = blockIdx.x * 128;

    float acc[2][8][4];
#pragma unroll
    for (int mt = 0; mt < 2; mt++)
#pragma unroll
        for (int nt = 0; nt < 8; nt++)
#pragma unroll
            for (int e = 0; e < 4; e++) acc[mt][nt][e] = 0.f;

    int lr = t >> 1;
    int s2 = (t & 1) * 2;

    // ---- Phase 1 prologue ----
#pragma unroll
    for (int c = 0; c < 2; c++) {
        int kc = c;
#pragma unroll
        for (int p = 0; p < 2; p++) {
            const __nv_bfloat16* gA = p ? g_hid_lo : g_hid_hi;
            const __nv_bfloat16* gB = p ? g_W1Tlo : g_W1Thi;
            __nv_bfloat16* dA = sA + (c * 2 + p) * 5120;
            __nv_bfloat16* dB = sB + (c * 2 + p) * 5120;
#pragma unroll
            for (int s = 0; s < 2; s++) {
                int seg = s2 + s;
                cp16(smem_u32(dA + lr * 40 + seg * 8), gA + (size_t)(m0 + lr) * 2048 + kc * 32 + seg * 8);
                cp16(smem_u32(dB + lr * 40 + seg * 8), gB + (size_t)lr * 2048 + kc * 32 + seg * 8);
            }
        }
        cp_commit();
    }

    int lrow = lane & 15;
    int lk   = (lane >> 4) << 3;

    // ---- Phase 1 mainloop ----
    for (int i = 0; i < 64; i++) {
        if (i < 63) asm volatile("cp.async.wait_group 1;");
        else        asm volatile("cp.async.wait_group 0;");
        __syncthreads();

        int st = i & 1;
        const __nv_bfloat16* Ah = sA + (st * 2 + 0) * 5120;
        const __nv_bfloat16* Al = sA + (st * 2 + 1) * 5120;
        const __nv_bfloat16* Bh = sB + (st * 2 + 0) * 5120;
        const __nv_bfloat16* Bl = sB + (st * 2 + 1) * 5120;

#pragma unroll
        for (int ks = 0; ks < 2; ks++) {
            int ko = ks * 16 + lk;
            unsigned ah[2][4], al[2][4], bb[4][4];
#pragma unroll
            for (int mt = 0; mt < 2; mt++)
                ldsm4(ah[mt], smem_u32(Ah + (wm * 32 + mt * 16 + lrow) * 40 + ko));
#pragma unroll
            for (int mt = 0; mt < 2; mt++)
                ldsm4(al[mt], smem_u32(Al + (wm * 32 + mt * 16 + lrow) * 40 + ko));
#pragma unroll
            for (int g = 0; g < 4; g++)
                ldsm4(bb[g], smem_u32(Bh + (wn * 64 + g * 16 + lrow) * 40 + ko));
#pragma unroll
            for (int mt = 0; mt < 2; mt++)
#pragma unroll
                for (int nt = 0; nt < 8; nt++)
                    mma16816(acc[mt][nt], ah[mt], bb[nt >> 1][nt & 1], bb[nt >> 1][(nt & 1) + 2]);
#pragma unroll
            for (int mt = 0; mt < 2; mt++)
#pragma unroll
                for (int nt = 0; nt < 8; nt++)
                    mma16816(acc[mt][nt], al[mt], bb[nt >> 1][nt & 1], bb[nt >> 1][(nt & 1) + 2]);
#pragma unroll
            for (int g = 0; g < 4; g++)
                ldsm4(bb[g], smem_u32(Bl + (wn * 64 + g * 16 + lrow) * 40 + ko));
#pragma unroll
            for (int mt = 0; mt < 2; mt++)
#pragma unroll
                for (int nt = 0; nt < 8; nt++)
                    mma16816(acc[mt][nt], ah[mt], bb[nt >> 1][nt & 1], bb[nt >> 1][(nt & 1) + 2]);
        }
        __syncthreads();

        if (i + 2 < 64) {
            int kc = i + 2;
#pragma unroll
            for (int p = 0; p < 2; p++) {
                const __nv_bfloat16* gA = p ? g_hid_lo : g_hid_hi;
                const __nv_bfloat16* gB = p ? g_W1Tlo : g_W1Thi;
                __nv_bfloat16* dA = sA + (st * 2 + p) * 5120;
                __nv_bfloat16* dB = sB + (st * 2 + p) * 5120;
#pragma unroll
                for (int s = 0; s < 2; s++) {
                    int seg = s2 + s;
                    cp16(smem_u32(dA + lr * 40 + seg * 8), gA + (size_t)(m0 + lr) * 2048 + kc * 32 + seg * 8);
                    cp16(smem_u32(dB + lr * 40 + seg * 8), gB + (size_t)lr * 2048 + kc * 32 + seg * 8);
                }
            }
            cp_commit();
        }
    }

    // ---- softmax epilogue -> attn into SMEM ----
    float bias8[4][2];
#pragma unroll
    for (int g = 0; g < 4; g++) {
        bias8[g][0] = g_bias[g * 8 + (lane & 3) * 2];
        bias8[g][1] = g_bias[g * 8 + (lane & 3) * 2 + 1];
    }

#pragma unroll
    for (int mt = 0; mt < 2; mt++) {
#pragma unroll
        for (int h2 = 0; h2 < 2; h2++) {
            int r = wm * 32 + mt * 16 + (lane >> 2) + h2 * 8;
#pragma unroll
            for (int hd = 0; hd < 2; hd++) {
                float s[8];
#pragma unroll
                for (int g = 0; g < 4; g++) {
                    int nt = hd * 4 + g;
                    s[g * 2]     = acc[mt][nt][h2 * 2]     + bias8[g][0];
                    s[g * 2 + 1] = acc[mt][nt][h2 * 2 + 1] + bias8[g][1];
                }
                float mx = s[0];
#pragma unroll
                for (int e = 1; e < 8; e++) mx = fmaxf(mx, s[e]);
                mx = fmaxf(mx, __shfl_xor_sync(0xffffffffu, mx, 1));
                mx = fmaxf(mx, __shfl_xor_sync(0xffffffffu, mx, 2));
                float ex[8], sum = 0.f;
#pragma unroll
                for (int e = 0; e < 8; e++) { ex[e] = __expf(s[e] - mx); sum += ex[e]; }
                sum += __shfl_xor_sync(0xffffffffu, sum, 1);
                sum += __shfl_xor_sync(0xffffffffu, sum, 2);
                float inv = 1.0f / sum;
#pragma unroll
                for (int g = 0; g < 4; g++) {
                    int col = wn * 64 + hd * 32 + g * 8 + (lane & 3) * 2;
                    float a0 = ex[g * 2] * inv, a1 = ex[g * 2 + 1] * inv;
                    __nv_bfloat16 h0b, l0b, h1b, l1b;
                    split_bf16(a0, h0b, l0b);
                    split_bf16(a1, h1b, l1b);
                    int o = r * 136 + col;
                    *reinterpret_cast<__nv_bfloat162*>(attnS + o)          = __nv_bfloat162(h0b, h1b);
                    *reinterpret_cast<__nv_bfloat162*>(attnS + 17408 + o)  = __nv_bfloat162(l0b, l1b);
                }
            }
        }
    }
    __syncthreads();

    // ---- Phase 2: out = attn @ W2, 16 n-tiles, W2 double-buffered ----
    const __nv_bfloat16* Ah2 = attnS;
    const __nv_bfloat16* Al2 = attnS + 17408;
    int sg0 = (t & 1) * 8;

    // prologue: tiles 0,1
#pragma unroll
    for (int c = 0; c < 2; c++) {
        __nv_bfloat16* dSt = reinterpret_cast<__nv_bfloat16*>(smraw + W2ST_OFF + c * 69632);
#pragma unroll
        for (int p = 0; p < 2; p++) {
            const __nv_bfloat16* gB = p ? g_W2Tlo : g_W2Thi;
            __nv_bfloat16* dB = dSt + p * 17408;
#pragma unroll
            for (int s = 0; s < 8; s++) {
                int seg = sg0 + s;
                cp16(smem_u32(dB + lr * 136 + seg * 8), gB + (size_t)(c * 128 + lr) * 128 + seg * 8);
            }
        }
        cp_commit();
    }

    for (int ni = 0; ni < 16; ni++) {
        if (ni < 15) asm volatile("cp.async.wait_group 1;");
        else         asm volatile("cp.async.wait_group 0;");
        __syncthreads();

        int st = ni & 1;
        const __nv_bfloat16* Bh = reinterpret_cast<const __nv_bfloat16*>(smraw + W2ST_OFF + st * 69632);
        const __nv_bfloat16* Bl = Bh + 17408;
        int n0 = ni * 128;

        float acc2[2][8][4];
#pragma unroll
        for (int mt = 0; mt < 2; mt++)
#pragma unroll
            for (int nt = 0; nt < 8; nt++)
#pragma unroll
                for (int e = 0; e < 4; e++) acc2[mt][nt][e] = 0.f;

#pragma unroll
        for (int ks = 0; ks < 8; ks++) {
            int ko = ks * 16 + lk;
            unsigned ah[2][4], al[2][4], bb[4][4];
#pragma unroll
            for (int mt = 0; mt < 2; mt++)
                ldsm4(ah[mt], smem_u32(Ah2 + (wm * 32 + mt * 16 + lrow) * 136 + ko));
#pragma unroll
            for (int mt = 0; mt < 2; mt++)
                ldsm4(al[mt], smem_u32(Al2 + (wm * 32 + mt * 16 + lrow) * 136 + ko));
#pragma unroll
            for (int g = 0; g < 4; g++)
                ldsm4(bb[g], smem_u32(Bh + (wn * 64 + g * 16 + lrow) * 136 + ko));
#pragma unroll
            for (int mt = 0; mt < 2; mt++)
#pragma unroll
                for (int nt = 0; nt < 8; nt++)
                    mma16816(acc2[mt][nt], ah[mt], bb[nt >> 1][nt & 1], bb[nt >> 1][(nt & 1) + 2]);
#pragma unroll
            for (int mt = 0; mt < 2; mt++)
#pragma unroll
                for (int nt = 0; nt < 8; nt++)
                    mma16816(acc2[mt][nt], al[mt], bb[nt >> 1][nt & 1], bb[nt >> 1][(nt & 1) + 2]);
#pragma unroll
            for (int g = 0; g < 4; g++)
                ldsm4(bb[g], smem_u32(Bl + (wn * 64 + g * 16 + lrow) * 136 + ko));
#pragma unroll
            for (int mt = 0; mt < 2; mt++)
#pragma unroll
                for (int nt = 0; nt < 8; nt++)
                    mma16816(acc2[mt][nt], ah[mt], bb[nt >> 1][nt & 1], bb[nt >> 1][(nt & 1) + 2]);
        }
        __syncthreads();

        if (ni + 2 < 16) {
            int nc = ni + 2;
            __nv_bfloat16* dSt = reinterpret_cast<__nv_bfloat16*>(smraw + W2ST_OFF + st * 69632);
#pragma unroll
            for (int p = 0; p < 2; p++) {
                const __nv_bfloat16* gB = p ? g_W2Tlo : g_W2Thi;
                __nv_bfloat16* dB = dSt + p * 17408;
#pragma unroll
                for (int s = 0; s < 8; s++) {
                    int seg = sg0 + s;
                    cp16(smem_u32(dB + lr * 136 + seg * 8), gB + (size_t)(nc * 128 + lr) * 128 + seg * 8);
                }
            }
            cp_commit();
        }

        // store this n-tile
#pragma unroll
        for (int mt = 0; mt < 2; mt++) {
            int r0 = m0 + wm * 32 + mt * 16 + (lane >> 2);
#pragma unroll
            for (int nt = 0; nt < 8; nt++) {
                int col = n0 + wn * 64 + nt * 8 + (lane & 3) * 2;
                *reinterpret_cast<float2*>(&out[(size_t)r0 * 2048 + col]) =
                    make_float2(acc2[mt][nt][0], acc2[mt][nt][1]);
                *reinterpret_cast<float2*>(&out[(size_t)(r0 + 8) * 2048 + col]) =
                    make_float2(acc2[mt][nt][2], acc2[mt][nt][3]);
            }
        }
    }
}

// ---------------- launch ----------------
extern "C" void kernel_launch(void* const* d_in, const int* in_sizes, int n_in,
                              void* d_out, int out_size) {
    const float* hidden   = (const float*)d_in[0];
    const float* beliefs  = (const float*)d_in[1];
    const int*   mask     = (const int*)d_in[2];
    const float* goal_emb = (const float*)d_in[3];
    const float* goal_pri = (const float*)d_in[4];
    const float* Wq       = (const float*)d_in[5];
    const float* Wo       = (const float*)d_in[6];
    const float* log_temp = (const float*)d_in[7];
    float* out = (float*)d_out;

    cudaFuncSetAttribute(k_fused, cudaFuncAttributeMaxDynamicSharedMemorySize, FUSED_SMEM);

    k_convsum<<<dim3(64, 2), 256>>>(hidden);
    k_mean<<<8, 256>>>();
    k_q1024<<<128, 256>>>(Wq);
    k_rough<<<8192, 256>>>(beliefs, mask);
    k_topA<<<256, 256>>>();
    k_topB1<<<16, 512>>>();
    k_topB2prep<<<1, 1024>>>(beliefs, goal_emb, goal_pri, log_temp);
    k_W1<<<dim3(32, 4), 256>>>(Wq);
    k_W2<<<2048, 128>>>(Wo);
    k_fused<<<128, 256, FUSED_SMEM>>>(out);
}

// round 15
// speedup vs baseline: 1.1419x; 1.1419x over previous
#include <cuda_runtime.h>
#include <cuda_bf16.h>
#include <math.h>

// Problem dims
// B=4, T=4096 -> M=16384 rows; H=2048; D=256; NH=4; K=32; NB=65536; NG=16; NK=NH*K=128

// ---------------- device scratch (no allocations allowed) ----------------
__device__ float g_partial[64 * 2048];
__device__ float g_meanq[2048];
__device__ float g_q1024[1024];
__device__ float g_scores[65536];
__device__ float g_candV[8192];
__device__ int   g_candI[8192];
__device__ float g_cand2V[512];
__device__ int   g_cand2I[512];
__device__ float g_keys[32 * 256];
__device__ float g_vals[32 * 256];
__device__ float g_bias[32];
__device__ float g_temp[4];

// bf16 hi/lo split planes
__device__ __nv_bfloat16 g_hid_hi[16384 * 2048];
__device__ __nv_bfloat16 g_hid_lo[16384 * 2048];
__device__ __nv_bfloat16 g_W1Thi[128 * 2048];   // [nk][h]
__device__ __nv_bfloat16 g_W1Tlo[128 * 2048];
__device__ __nv_bfloat16 g_W2Thi[2048 * 128];   // [j][nk]
__device__ __nv_bfloat16 g_W2Tlo[2048 * 128];

// ---------------- PTX helpers ----------------
__device__ __forceinline__ unsigned smem_u32(const void* p) {
    return (unsigned)__cvta_generic_to_shared(p);
}
__device__ __forceinline__ void cp16(unsigned dst, const void* src) {
    asm volatile("cp.async.cg.shared.global [%0], [%1], 16;" :: "r"(dst), "l"(src));
}
__device__ __forceinline__ void cp_commit() { asm volatile("cp.async.commit_group;"); }
__device__ __forceinline__ void ldsm4(unsigned* r, unsigned addr) {
    asm volatile("ldmatrix.sync.aligned.m8n8.x4.shared.b16 {%0,%1,%2,%3}, [%4];"
        : "=r"(r[0]), "=r"(r[1]), "=r"(r[2]), "=r"(r[3]) : "r"(addr));
}
// b0 = k[0:8] half, b1 = k[8:16] half of the SAME n8 subtile (non-contiguous regs)
__device__ __forceinline__ void mma16816(float* c, const unsigned* a, unsigned b0, unsigned b1) {
    asm volatile("mma.sync.aligned.m16n8k16.row.col.f32.bf16.bf16.f32 "
        "{%0,%1,%2,%3}, {%4,%5,%6,%7}, {%8,%9}, {%0,%1,%2,%3};"
        : "+f"(c[0]), "+f"(c[1]), "+f"(c[2]), "+f"(c[3])
        : "r"(a[0]), "r"(a[1]), "r"(a[2]), "r"(a[3]), "r"(b0), "r"(b1));
}
__device__ __forceinline__ void split_bf16(float x, __nv_bfloat16& h, __nv_bfloat16& l) {
    h = __float2bfloat16(x);
    l = __float2bfloat16(x - __bfloat162float(h));
}

// ---------------- 1) column sums + hi/lo split of hidden (R10 scalar, grid 64x8) ----------------
__global__ void k_convsum(const float* __restrict__ hidden) {
    int col = blockIdx.y * 256 + threadIdx.x;
    int r0  = blockIdx.x * 256;
    float s = 0.f;
#pragma unroll 4
    for (int r = 0; r < 256; r++) {
        size_t idx = (size_t)(r0 + r) * 2048 + col;
        float x = hidden[idx];
        s += x;
        __nv_bfloat16 h, l;
        split_bf16(x, h, l);
        g_hid_hi[idx] = h;
        g_hid_lo[idx] = l;
    }
    g_partial[blockIdx.x * 2048 + col] = s;
}

__global__ void k_mean() {
    int col = blockIdx.x * 256 + threadIdx.x;
    float s = 0.f;
#pragma unroll
    for (int r = 0; r < 64; r++) s += g_partial[r * 2048 + col];
    g_meanq[col] = s * (1.0f / 16384.0f);
}

// ---------------- 2) q1024 = Wq @ mean_query ----------------
__global__ void k_q1024(const float* __restrict__ Wq) {
    int row  = (blockIdx.x << 3) + (threadIdx.x >> 5);
    int lane = threadIdx.x & 31;
    const float* wp = Wq + (size_t)row * 2048;
    float s = 0.f;
#pragma unroll 8
    for (int j = 0; j < 64; j++) s += wp[j * 32 + lane] * g_meanq[j * 32 + lane];
#pragma unroll
    for (int off = 16; off > 0; off >>= 1) s += __shfl_xor_sync(0xffffffffu, s, off);
    if (lane == 0) g_q1024[row] = s;
}

// ---------------- 3) rough scores ----------------
__global__ void k_rough(const float* __restrict__ beliefs, const int* __restrict__ mask) {
    __shared__ float rqS[256];
    int t = threadIdx.x;
    rqS[t] = 0.25f * (g_q1024[t] + g_q1024[256 + t] + g_q1024[512 + t] + g_q1024[768 + t]);
    __syncthreads();
    int w    = (blockIdx.x << 3) + (t >> 5);
    int lane = t & 31;
    const float* bp = beliefs + (size_t)w * 256;
    float dot = 0.f, ss = 0.f;
#pragma unroll
    for (int j = 0; j < 8; j++) {
        float v = bp[j * 32 + lane];
        dot += v * rqS[j * 32 + lane];
        ss  += v * v;
    }
#pragma unroll
    for (int off = 16; off > 0; off >>= 1) {
        dot += __shfl_xor_sync(0xffffffffu, dot, off);
        ss  += __shfl_xor_sync(0xffffffffu, ss, off);
    }
    if (lane == 0) {
        float score = dot / fmaxf(sqrtf(ss), 1e-8f);
        g_scores[w] = (mask[w] != 0) ? score : -1e30f;
    }
}

// ---------------- 4) top-32 via HIERARCHICAL rank counting ----------------
__global__ void k_topA() {
    __shared__ __align__(16) float sv[256];
    int t = threadIdx.x;
    float v = g_scores[blockIdx.x * 256 + t];
    sv[t] = v;
    __syncthreads();
    int rank = 0;
#pragma unroll 16
    for (int j4 = 0; j4 < 64; j4++) {
        float4 f = *reinterpret_cast<const float4*>(&sv[j4 * 4]);
        int j = j4 * 4;
        rank += (f.x > v) || (f.x == v && (j + 0) < t);
        rank += (f.y > v) || (f.y == v && (j + 1) < t);
        rank += (f.z > v) || (f.z == v && (j + 2) < t);
        rank += (f.w > v) || (f.w == v && (j + 3) < t);
    }
    if (rank < 32) {
        g_candV[blockIdx.x * 32 + rank] = v;
        g_candI[blockIdx.x * 32 + rank] = blockIdx.x * 256 + t;
    }
}

__global__ void k_topB1() {
    __shared__ __align__(16) float sv[512];
    int t = threadIdx.x;
    int base = blockIdx.x * 512;
    float v = g_candV[base + t];
    sv[t] = v;
    __syncthreads();
    int rank = 0;
#pragma unroll 16
    for (int j4 = 0; j4 < 128; j4++) {
        float4 f = *reinterpret_cast<const float4*>(&sv[j4 * 4]);
        int j = j4 * 4;
        rank += (f.x > v) || (f.x == v && (j + 0) < t);
        rank += (f.y > v) || (f.y == v && (j + 1) < t);
        rank += (f.z > v) || (f.z == v && (j + 2) < t);
        rank += (f.w > v) || (f.w == v && (j + 3) < t);
    }
    if (rank < 32) {
        g_cand2V[blockIdx.x * 32 + rank] = v;
        g_cand2I[blockIdx.x * 32 + rank] = g_candI[base + t];
    }
}

// ---------------- 5) topB2 (final rank) + keys/values/bias/temp, fused (validated R14) ----------------
__global__ void k_topB2prep(const float* __restrict__ beliefs,
                            const float* __restrict__ ge,
                            const float* __restrict__ gp,
                            const float* __restrict__ lt) {
    __shared__ __align__(16) float sv[512];
    __shared__ int topkS[32];
    __shared__ float gA[16][256];
    __shared__ float gpS[16];
    int t = threadIdx.x, w = t >> 5, lane = t & 31;

    if (t < 512) sv[t] = g_cand2V[t];
    if (t < 4)  g_temp[t] = fmaxf(expf(lt[t]), 0.1f);
    if (t < 16) gpS[t] = gp[t];
    __syncthreads();

    if (t < 512) {
        float v = sv[t];
        int rank = 0;
#pragma unroll 16
        for (int j4 = 0; j4 < 128; j4++) {
            float4 f = *reinterpret_cast<const float4*>(&sv[j4 * 4]);
            int j = j4 * 4;
            rank += (f.x > v) || (f.x == v && (j + 0) < t);
            rank += (f.y > v) || (f.y == v && (j + 1) < t);
            rank += (f.z > v) || (f.z == v && (j + 2) < t);
            rank += (f.w > v) || (f.w == v && (j + 3) < t);
        }
        if (rank < 32) topkS[rank] = g_cand2I[t];
    }
    __syncthreads();

    int idx = topkS[w];
    float v[8], kreg[8];
    float ss = 0.f;
#pragma unroll
    for (int j = 0; j < 8; j++) {
        v[j] = beliefs[(size_t)idx * 256 + j * 32 + lane];
        ss += v[j] * v[j];
    }
#pragma unroll
    for (int off = 16; off > 0; off >>= 1) ss += __shfl_xor_sync(0xffffffffu, ss, off);
    float inv = 1.0f / fmaxf(sqrtf(ss), 1e-8f);
#pragma unroll
    for (int j = 0; j < 8; j++) {
        kreg[j] = v[j] * inv;
        g_keys[w * 256 + j * 32 + lane] = kreg[j];
        g_vals[w * 256 + j * 32 + lane] = v[j];
    }
    if (w < 16) {
        float gv[8]; float gs = 0.f;
#pragma unroll
        for (int j = 0; j < 8; j++) {
            gv[j] = ge[w * 256 + j * 32 + lane];
            gs += gv[j] * gv[j];
        }
#pragma unroll
        for (int off = 16; off > 0; off >>= 1) gs += __shfl_xor_sync(0xffffffffu, gs, off);
        float gi = 1.0f / fmaxf(sqrtf(gs), 1e-8f);
#pragma unroll
        for (int j = 0; j < 8; j++) gA[w][j * 32 + lane] = gv[j] * gi;
    }
    __syncthreads();
    float best = -INFINITY;
#pragma unroll
    for (int g = 0; g < 16; g++) {
        float d = 0.f;
#pragma unroll
        for (int j = 0; j < 8; j++) d += kreg[j] * gA[g][j * 32 + lane];
#pragma unroll
        for (int off = 16; off > 0; off >>= 1) d += __shfl_xor_sync(0xffffffffu, d, off);
        best = fmaxf(best, d * gpS[g]);
    }
    if (lane == 0) g_bias[w] = best;
}

// ---------------- 6) W1T[nk][h], bf16 hi/lo ----------------
__global__ void __launch_bounds__(256) k_W1(const float* __restrict__ Wq) {
    __shared__ float keysS[32 * 256];
    __shared__ float aS[8 * 64];
    int t = threadIdx.x;
    int h0 = blockIdx.x * 64;
    int head = blockIdx.y;
#pragma unroll
    for (int i = 0; i < 32; i++) keysS[t + i * 256] = g_keys[t + i * 256];
    float acc[8];
#pragma unroll
    for (int j = 0; j < 8; j++) acc[j] = 0.f;
    int k4 = t >> 6, hl = t & 63;
    for (int dc = 0; dc < 32; dc++) {
        __syncthreads();
#pragma unroll
        for (int i = 0; i < 2; i++) {
            int e = t + i * 256;
            int dd = e >> 6, hh = e & 63;
            aS[dd * 64 + hh] = Wq[(size_t)(head * 256 + dc * 8 + dd) * 2048 + h0 + hh];
        }
        __syncthreads();
#pragma unroll
        for (int dd = 0; dd < 8; dd++) {
            float a = aS[dd * 64 + hl];
            int dg = dc * 8 + dd;
#pragma unroll
            for (int j = 0; j < 8; j++) acc[j] += a * keysS[(k4 * 8 + j) * 256 + dg];
        }
    }
    float scale = g_temp[head] * 0.0625f;
#pragma unroll
    for (int j = 0; j < 8; j++) {
        float v = acc[j] * scale;
        __nv_bfloat16 h, l;
        split_bf16(v, h, l);
        size_t o = (size_t)(head * 32 + k4 * 8 + j) * 2048 + h0 + hl;
        g_W1Thi[o] = h;
        g_W1Tlo[o] = l;
    }
}

// ---------------- 7) W2T[j][nk], bf16 hi/lo ----------------
__global__ void __launch_bounds__(128) k_W2(const float* __restrict__ Wo) {
    __shared__ float woS[1024];
    __shared__ float valT[256 * 33];
    int t = threadIdx.x;
    int j = blockIdx.x;
#pragma unroll
    for (int i = 0; i < 8; i++) woS[t + i * 128] = Wo[(size_t)j * 1024 + t + i * 128];
#pragma unroll
    for (int i = 0; i < 64; i++) {
        int e = t + i * 128;
        int k = e >> 8, d = e & 255;
        valT[d * 33 + k] = g_vals[e];
    }
    __syncthreads();
    int n = t >> 5, k = t & 31;
    float acc = 0.f;
#pragma unroll 8
    for (int d = 0; d < 256; d++) acc += valT[d * 33 + k] * woS[n * 256 + d];
    __nv_bfloat16 h, l;
    split_bf16(acc, h, l);
    g_W2Thi[(size_t)j * 128 + t] = h;
    g_W2Tlo[(size_t)j * 128 + t] = l;
}

// ---------------- 8) FUSED (verbatim R10): attn in SMEM, then out = attn@W2 ----------------
static constexpr int ATTN_OFF  = 0;
static constexpr int PIPE_OFF  = 69632;
static constexpr int W2ST_OFF  = 69632;
static constexpr int FUSED_SMEM = 208896;

__global__ void __launch_bounds__(256) k_fused(float* __restrict__ out) {
    extern __shared__ __align__(16) char smraw[];
    __nv_bfloat16* attnS = reinterpret_cast<__nv_bfloat16*>(smraw + ATTN_OFF);
    __nv_bfloat16* sA = reinterpret_cast<__nv_bfloat16*>(smraw + PIPE_OFF);
    __nv_bfloat16* sB = sA + 20480;

    int t = threadIdx.x;
    int lane = t & 31, w = t >> 5;
    int wm = w & 3, wn = w >> 2;
    int m0 = blockIdx.x * 128;

    float acc[2][8][4];
#pragma unroll
    for (int mt = 0; mt < 2; mt++)
#pragma unroll
        for (int nt = 0; nt < 8; nt++)
#pragma unroll
            for (int e = 0; e < 4; e++) acc[mt][nt][e] = 0.f;

    int lr = t >> 1;
    int s2 = (t & 1) * 2;

    // ---- Phase 1 prologue ----
#pragma unroll
    for (int c = 0; c < 2; c++) {
        int kc = c;
#pragma unroll
        for (int p = 0; p < 2; p++) {
            const __nv_bfloat16* gA = p ? g_hid_lo : g_hid_hi;
            const __nv_bfloat16* gB = p ? g_W1Tlo : g_W1Thi;
            __nv_bfloat16* dA = sA + (c * 2 + p) * 5120;
            __nv_bfloat16* dB = sB + (c * 2 + p) * 5120;
#pragma unroll
            for (int s = 0; s < 2; s++) {
                int seg = s2 + s;
                cp16(smem_u32(dA + lr * 40 + seg * 8), gA + (size_t)(m0 + lr) * 2048 + kc * 32 + seg * 8);
                cp16(smem_u32(dB + lr * 40 + seg * 8), gB + (size_t)lr * 2048 + kc * 32 + seg * 8);
            }
        }
        cp_commit();
    }

    int lrow = lane & 15;
    int lk   = (lane >> 4) << 3;

    // ---- Phase 1 mainloop ----
    for (int i = 0; i < 64; i++) {
        if (i < 63) asm volatile("cp.async.wait_group 1;");
        else        asm volatile("cp.async.wait_group 0;");
        __syncthreads();

        int st = i & 1;
        const __nv_bfloat16* Ah = sA + (st * 2 + 0) * 5120;
        const __nv_bfloat16* Al = sA + (st * 2 + 1) * 5120;
        const __nv_bfloat16* Bh = sB + (st * 2 + 0) * 5120;
        const __nv_bfloat16* Bl = sB + (st * 2 + 1) * 5120;

#pragma unroll
        for (int ks = 0; ks < 2; ks++) {
            int ko = ks * 16 + lk;
            unsigned ah[2][4], al[2][4], bb[4][4];
#pragma unroll
            for (int mt = 0; mt < 2; mt++)
                ldsm4(ah[mt], smem_u32(Ah + (wm * 32 + mt * 16 + lrow) * 40 + ko));
#pragma unroll
            for (int mt = 0; mt < 2; mt++)
                ldsm4(al[mt], smem_u32(Al + (wm * 32 + mt * 16 + lrow) * 40 + ko));
#pragma unroll
            for (int g = 0; g < 4; g++)
                ldsm4(bb[g], smem_u32(Bh + (wn * 64 + g * 16 + lrow) * 40 + ko));
#pragma unroll
            for (int mt = 0; mt < 2; mt++)
#pragma unroll
                for (int nt = 0; nt < 8; nt++)
                    mma16816(acc[mt][nt], ah[mt], bb[nt >> 1][nt & 1], bb[nt >> 1][(nt & 1) + 2]);
#pragma unroll
            for (int mt = 0; mt < 2; mt++)
#pragma unroll
                for (int nt = 0; nt < 8; nt++)
                    mma16816(acc[mt][nt], al[mt], bb[nt >> 1][nt & 1], bb[nt >> 1][(nt & 1) + 2]);
#pragma unroll
            for (int g = 0; g < 4; g++)
                ldsm4(bb[g], smem_u32(Bl + (wn * 64 + g * 16 + lrow) * 40 + ko));
#pragma unroll
            for (int mt = 0; mt < 2; mt++)
#pragma unroll
                for (int nt = 0; nt < 8; nt++)
                    mma16816(acc[mt][nt], ah[mt], bb[nt >> 1][nt & 1], bb[nt >> 1][(nt & 1) + 2]);
        }
        __syncthreads();

        if (i + 2 < 64) {
            int kc = i + 2;
#pragma unroll
            for (int p = 0; p < 2; p++) {
                const __nv_bfloat16* gA = p ? g_hid_lo : g_hid_hi;
                const __nv_bfloat16* gB = p ? g_W1Tlo : g_W1Thi;
                __nv_bfloat16* dA = sA + (st * 2 + p) * 5120;
                __nv_bfloat16* dB = sB + (st * 2 + p) * 5120;
#pragma unroll
                for (int s = 0; s < 2; s++) {
                    int seg = s2 + s;
                    cp16(smem_u32(dA + lr * 40 + seg * 8), gA + (size_t)(m0 + lr) * 2048 + kc * 32 + seg * 8);
                    cp16(smem_u32(dB + lr * 40 + seg * 8), gB + (size_t)lr * 2048 + kc * 32 + seg * 8);
                }
            }
            cp_commit();
        }
    }

    // ---- softmax epilogue -> attn into SMEM ----
    float bias8[4][2];
#pragma unroll
    for (int g = 0; g < 4; g++) {
        bias8[g][0] = g_bias[g * 8 + (lane & 3) * 2];
        bias8[g][1] = g_bias[g * 8 + (lane & 3) * 2 + 1];
    }

#pragma unroll
    for (int mt = 0; mt < 2; mt++) {
#pragma unroll
        for (int h2 = 0; h2 < 2; h2++) {
            int r = wm * 32 + mt * 16 + (lane >> 2) + h2 * 8;
#pragma unroll
            for (int hd = 0; hd < 2; hd++) {
                float s[8];
#pragma unroll
                for (int g = 0; g < 4; g++) {
                    int nt = hd * 4 + g;
                    s[g * 2]     = acc[mt][nt][h2 * 2]     + bias8[g][0];
                    s[g * 2 + 1] = acc[mt][nt][h2 * 2 + 1] + bias8[g][1];
                }
                float mx = s[0];
#pragma unroll
                for (int e = 1; e < 8; e++) mx = fmaxf(mx, s[e]);
                mx = fmaxf(mx, __shfl_xor_sync(0xffffffffu, mx, 1));
                mx = fmaxf(mx, __shfl_xor_sync(0xffffffffu, mx, 2));
                float ex[8], sum = 0.f;
#pragma unroll
                for (int e = 0; e < 8; e++) { ex[e] = __expf(s[e] - mx); sum += ex[e]; }
                sum += __shfl_xor_sync(0xffffffffu, sum, 1);
                sum += __shfl_xor_sync(0xffffffffu, sum, 2);
                float inv = 1.0f / sum;
#pragma unroll
                for (int g = 0; g < 4; g++) {
                    int col = wn * 64 + hd * 32 + g * 8 + (lane & 3) * 2;
                    float a0 = ex[g * 2] * inv, a1 = ex[g * 2 + 1] * inv;
                    __nv_bfloat16 h0b, l0b, h1b, l1b;
                    split_bf16(a0, h0b, l0b);
                    split_bf16(a1, h1b, l1b);
                    int o = r * 136 + col;
                    *reinterpret_cast<__nv_bfloat162*>(attnS + o)          = __nv_bfloat162(h0b, h1b);
                    *reinterpret_cast<__nv_bfloat162*>(attnS + 17408 + o)  = __nv_bfloat162(l0b, l1b);
                }
            }
        }
    }
    __syncthreads();

    // ---- Phase 2: out = attn @ W2, 16 n-tiles, W2 double-buffered ----
    const __nv_bfloat16* Ah2 = attnS;
    const __nv_bfloat16* Al2 = attnS + 17408;
    int sg0 = (t & 1) * 8;

    // prologue: tiles 0,1
#pragma unroll
    for (int c = 0; c < 2; c++) {
        __nv_bfloat16* dSt = reinterpret_cast<__nv_bfloat16*>(smraw + W2ST_OFF + c * 69632);
#pragma unroll
        for (int p = 0; p < 2; p++) {
            const __nv_bfloat16* gB = p ? g_W2Tlo : g_W2Thi;
            __nv_bfloat16* dB = dSt + p * 17408;
#pragma unroll
            for (int s = 0; s < 8; s++) {
                int seg = sg0 + s;
                cp16(smem_u32(dB + lr * 136 + seg * 8), gB + (size_t)(c * 128 + lr) * 128 + seg * 8);
            }
        }
        cp_commit();
    }

    for (int ni = 0; ni < 16; ni++) {
        if (ni < 15) asm volatile("cp.async.wait_group 1;");
        else         asm volatile("cp.async.wait_group 0;");
        __syncthreads();

        int st = ni & 1;
        const __nv_bfloat16* Bh = reinterpret_cast<const __nv_bfloat16*>(smraw + W2ST_OFF + st * 69632);
        const __nv_bfloat16* Bl = Bh + 17408;
        int n0 = ni * 128;

        float acc2[2][8][4];
#pragma unroll
        for (int mt = 0; mt < 2; mt++)
#pragma unroll
            for (int nt = 0; nt < 8; nt++)
#pragma unroll
                for (int e = 0; e < 4; e++) acc2[mt][nt][e] = 0.f;

#pragma unroll
        for (int ks = 0; ks < 8; ks++) {
            int ko = ks * 16 + lk;
            unsigned ah[2][4], al[2][4], bb[4][4];
#pragma unroll
            for (int mt = 0; mt < 2; mt++)
                ldsm4(ah[mt], smem_u32(Ah2 + (wm * 32 + mt * 16 + lrow) * 136 + ko));
#pragma unroll
            for (int mt = 0; mt < 2; mt++)
                ldsm4(al[mt], smem_u32(Al2 + (wm * 32 + mt * 16 + lrow) * 136 + ko));
#pragma unroll
            for (int g = 0; g < 4; g++)
                ldsm4(bb[g], smem_u32(Bh + (wn * 64 + g * 16 + lrow) * 136 + ko));
#pragma unroll
            for (int mt = 0; mt < 2; mt++)
#pragma unroll
                for (int nt = 0; nt < 8; nt++)
                    mma16816(acc2[mt][nt], ah[mt], bb[nt >> 1][nt & 1], bb[nt >> 1][(nt & 1) + 2]);
#pragma unroll
            for (int mt = 0; mt < 2; mt++)
#pragma unroll
                for (int nt = 0; nt < 8; nt++)
                    mma16816(acc2[mt][nt], al[mt], bb[nt >> 1][nt & 1], bb[nt >> 1][(nt & 1) + 2]);
#pragma unroll
            for (int g = 0; g < 4; g++)
                ldsm4(bb[g], smem_u32(Bl + (wn * 64 + g * 16 + lrow) * 136 + ko));
#pragma unroll
            for (int mt = 0; mt < 2; mt++)
#pragma unroll
                for (int nt = 0; nt < 8; nt++)
                    mma16816(acc2[mt][nt], ah[mt], bb[nt >> 1][nt & 1], bb[nt >> 1][(nt & 1) + 2]);
        }
        __syncthreads();

        if (ni + 2 < 16) {
            int nc = ni + 2;
            __nv_bfloat16* dSt = reinterpret_cast<__nv_bfloat16*>(smraw + W2ST_OFF + st * 69632);
#pragma unroll
            for (int p = 0; p < 2; p++) {
                const __nv_bfloat16* gB = p ? g_W2Tlo : g_W2Thi;
                __nv_bfloat16* dB = dSt + p * 17408;
#pragma unroll
                for (int s = 0; s < 8; s++) {
                    int seg = sg0 + s;
                    cp16(smem_u32(dB + lr * 136 + seg * 8), gB + (size_t)(nc * 128 + lr) * 128 + seg * 8);
                }
            }
            cp_commit();
        }

        // store this n-tile
#pragma unroll
        for (int mt = 0; mt < 2; mt++) {
            int r0 = m0 + wm * 32 + mt * 16 + (lane >> 2);
#pragma unroll
            for (int nt = 0; nt < 8; nt++) {
                int col = n0 + wn * 64 + nt * 8 + (lane & 3) * 2;
                *reinterpret_cast<float2*>(&out[(size_t)r0 * 2048 + col]) =
                    make_float2(acc2[mt][nt][0], acc2[mt][nt][1]);
                *reinterpret_cast<float2*>(&out[(size_t)(r0 + 8) * 2048 + col]) =
                    make_float2(acc2[mt][nt][2], acc2[mt][nt][3]);
            }
        }
    }
}

// ---------------- launch ----------------
extern "C" void kernel_launch(void* const* d_in, const int* in_sizes, int n_in,
                              void* d_out, int out_size) {
    const float* hidden   = (const float*)d_in[0];
    const float* beliefs  = (const float*)d_in[1];
    const int*   mask     = (const int*)d_in[2];
    const float* goal_emb = (const float*)d_in[3];
    const float* goal_pri = (const float*)d_in[4];
    const float* Wq       = (const float*)d_in[5];
    const float* Wo       = (const float*)d_in[6];
    const float* log_temp = (const float*)d_in[7];
    float* out = (float*)d_out;

    cudaFuncSetAttribute(k_fused, cudaFuncAttributeMaxDynamicSharedMemorySize, FUSED_SMEM);

    k_convsum<<<dim3(64, 8), 256>>>(hidden);
    k_mean<<<8, 256>>>();
    k_q1024<<<128, 256>>>(Wq);
    k_rough<<<8192, 256>>>(beliefs, mask);
    k_topA<<<256, 256>>>();
    k_topB1<<<16, 512>>>();
    k_topB2prep<<<1, 1024>>>(beliefs, goal_emb, goal_pri, log_temp);
    k_W1<<<dim3(32, 4), 256>>>(Wq);
    k_W2<<<2048, 128>>>(Wo);
    k_fused<<<128, 256, FUSED_SMEM>>>(out);
}

// round 16
// speedup vs baseline: 1.2300x; 1.0772x over previous
#include <cuda_runtime.h>
#include <cuda_bf16.h>
#include <math.h>

// Problem dims
// B=4, T=4096 -> M=16384 rows; H=2048; D=256; NH=4; K=32; NB=65536; NG=16; NK=NH*K=128

// ---------------- device scratch (no allocations allowed) ----------------
__device__ float g_partial[64 * 2048];
__device__ float g_meanq[2048];
__device__ float g_q1024[1024];
__device__ float g_scores[65536];
__device__ float g_candV[8192];
__device__ int   g_candI[8192];
__device__ float g_cand2V[512];
__device__ int   g_cand2I[512];
__device__ float g_keys[32 * 256];
__device__ float g_vals[32 * 256];
__device__ float g_bias[32];
__device__ float g_temp[4];

// bf16 hi/lo split planes
__device__ __nv_bfloat16 g_hid_hi[16384 * 2048];
__device__ __nv_bfloat16 g_hid_lo[16384 * 2048];
__device__ __nv_bfloat16 g_W1Thi[128 * 2048];   // [nk][h]
__device__ __nv_bfloat16 g_W1Tlo[128 * 2048];
// W2 planes: per-tile contiguous (tile = 128 j-rows x 128 nk), 16B-chunk swizzled:
// element (j, nk) at tile*16384 + (j&127)*128 + (((nk>>3)^(j&7))<<3) + (nk&7)
__device__ __nv_bfloat16 g_W2Thi[2048 * 128];
__device__ __nv_bfloat16 g_W2Tlo[2048 * 128];

// ---------------- PTX helpers ----------------
__device__ __forceinline__ unsigned smem_u32(const void* p) {
    return (unsigned)__cvta_generic_to_shared(p);
}
__device__ __forceinline__ void cp16(unsigned dst, const void* src) {
    asm volatile("cp.async.cg.shared.global [%0], [%1], 16;" :: "r"(dst), "l"(src));
}
__device__ __forceinline__ void cp_commit() { asm volatile("cp.async.commit_group;"); }
__device__ __forceinline__ void ldsm4(unsigned* r, unsigned addr) {
    asm volatile("ldmatrix.sync.aligned.m8n8.x4.shared.b16 {%0,%1,%2,%3}, [%4];"
        : "=r"(r[0]), "=r"(r[1]), "=r"(r[2]), "=r"(r[3]) : "r"(addr));
}
// b0 = k[0:8] half, b1 = k[8:16] half of the SAME n8 subtile (non-contiguous regs)
__device__ __forceinline__ void mma16816(float* c, const unsigned* a, unsigned b0, unsigned b1) {
    asm volatile("mma.sync.aligned.m16n8k16.row.col.f32.bf16.bf16.f32 "
        "{%0,%1,%2,%3}, {%4,%5,%6,%7}, {%8,%9}, {%0,%1,%2,%3};"
        : "+f"(c[0]), "+f"(c[1]), "+f"(c[2]), "+f"(c[3])
        : "r"(a[0]), "r"(a[1]), "r"(a[2]), "r"(a[3]), "r"(b0), "r"(b1));
}
__device__ __forceinline__ void split_bf16(float x, __nv_bfloat16& h, __nv_bfloat16& l) {
    h = __float2bfloat16(x);
    l = __float2bfloat16(x - __bfloat162float(h));
}
__device__ __forceinline__ void mbar_init(unsigned addr, unsigned cnt) {
    asm volatile("mbarrier.init.shared.b64 [%0], %1;" :: "r"(addr), "r"(cnt) : "memory");
}
__device__ __forceinline__ void mbar_expect_tx(unsigned addr, unsigned bytes) {
    asm volatile("mbarrier.arrive.expect_tx.shared.b64 _, [%0], %1;" :: "r"(addr), "r"(bytes) : "memory");
}
__device__ __forceinline__ void bulk_ld(unsigned dst, const void* src, unsigned bytes, unsigned mbar) {
    asm volatile("cp.async.bulk.shared::cta.global.mbarrier::complete_tx::bytes [%0], [%1], %2, [%3];"
        :: "r"(dst), "l"(src), "r"(bytes), "r"(mbar) : "memory");
}
__device__ __forceinline__ void mbar_wait(unsigned addr, unsigned parity) {
    asm volatile(
        "{\n\t.reg .pred P;\n\t"
        "MBWAIT_%=:\n\t"
        "mbarrier.try_wait.parity.acquire.cta.shared::cta.b64 P, [%0], %1;\n\t"
        "@!P bra MBWAIT_%=;\n\t"
        "}" :: "r"(addr), "r"(parity) : "memory");
}

// ---------------- 1) column sums + hi/lo split of hidden (validated scalar, grid 64x8) ----------------
__global__ void k_convsum(const float* __restrict__ hidden) {
    int col = blockIdx.y * 256 + threadIdx.x;
    int r0  = blockIdx.x * 256;
    float s = 0.f;
#pragma unroll 4
    for (int r = 0; r < 256; r++) {
        size_t idx = (size_t)(r0 + r) * 2048 + col;
        float x = hidden[idx];
        s += x;
        __nv_bfloat16 h, l;
        split_bf16(x, h, l);
        g_hid_hi[idx] = h;
        g_hid_lo[idx] = l;
    }
    g_partial[blockIdx.x * 2048 + col] = s;
}

__global__ void k_mean() {
    int col = blockIdx.x * 256 + threadIdx.x;
    float s = 0.f;
#pragma unroll
    for (int r = 0; r < 64; r++) s += g_partial[r * 2048 + col];
    g_meanq[col] = s * (1.0f / 16384.0f);
}

// ---------------- 2) q1024 = Wq @ mean_query ----------------
__global__ void k_q1024(const float* __restrict__ Wq) {
    int row  = (blockIdx.x << 3) + (threadIdx.x >> 5);
    int lane = threadIdx.x & 31;
    const float* wp = Wq + (size_t)row * 2048;
    float s = 0.f;
#pragma unroll 8
    for (int j = 0; j < 64; j++) s += wp[j * 32 + lane] * g_meanq[j * 32 + lane];
#pragma unroll
    for (int off = 16; off > 0; off >>= 1) s += __shfl_xor_sync(0xffffffffu, s, off);
    if (lane == 0) g_q1024[row] = s;
}

// ---------------- 3) rough scores ----------------
__global__ void k_rough(const float* __restrict__ beliefs, const int* __restrict__ mask) {
    __shared__ float rqS[256];
    int t = threadIdx.x;
    rqS[t] = 0.25f * (g_q1024[t] + g_q1024[256 + t] + g_q1024[512 + t] + g_q1024[768 + t]);
    __syncthreads();
    int w    = (blockIdx.x << 3) + (t >> 5);
    int lane = t & 31;
    const float* bp = beliefs + (size_t)w * 256;
    float dot = 0.f, ss = 0.f;
#pragma unroll
    for (int j = 0; j < 8; j++) {
        float v = bp[j * 32 + lane];
        dot += v * rqS[j * 32 + lane];
        ss  += v * v;
    }
#pragma unroll
    for (int off = 16; off > 0; off >>= 1) {
        dot += __shfl_xor_sync(0xffffffffu, dot, off);
        ss  += __shfl_xor_sync(0xffffffffu, ss, off);
    }
    if (lane == 0) {
        float score = dot / fmaxf(sqrtf(ss), 1e-8f);
        g_scores[w] = (mask[w] != 0) ? score : -1e30f;
    }
}

// ---------------- 4) top-32 via HIERARCHICAL rank counting ----------------
__global__ void k_topA() {
    __shared__ __align__(16) float sv[256];
    int t = threadIdx.x;
    float v = g_scores[blockIdx.x * 256 + t];
    sv[t] = v;
    __syncthreads();
    int rank = 0;
#pragma unroll 16
    for (int j4 = 0; j4 < 64; j4++) {
        float4 f = *reinterpret_cast<const float4*>(&sv[j4 * 4]);
        int j = j4 * 4;
        rank += (f.x > v) || (f.x == v && (j + 0) < t);
        rank += (f.y > v) || (f.y == v && (j + 1) < t);
        rank += (f.z > v) || (f.z == v && (j + 2) < t);
        rank += (f.w > v) || (f.w == v && (j + 3) < t);
    }
    if (rank < 32) {
        g_candV[blockIdx.x * 32 + rank] = v;
        g_candI[blockIdx.x * 32 + rank] = blockIdx.x * 256 + t;
    }
}

__global__ void k_topB1() {
    __shared__ __align__(16) float sv[512];
    int t = threadIdx.x;
    int base = blockIdx.x * 512;
    float v = g_candV[base + t];
    sv[t] = v;
    __syncthreads();
    int rank = 0;
#pragma unroll 16
    for (int j4 = 0; j4 < 128; j4++) {
        float4 f = *reinterpret_cast<const float4*>(&sv[j4 * 4]);
        int j = j4 * 4;
        rank += (f.x > v) || (f.x == v && (j + 0) < t);
        rank += (f.y > v) || (f.y == v && (j + 1) < t);
        rank += (f.z > v) || (f.z == v && (j + 2) < t);
        rank += (f.w > v) || (f.w == v && (j + 3) < t);
    }
    if (rank < 32) {
        g_cand2V[blockIdx.x * 32 + rank] = v;
        g_cand2I[blockIdx.x * 32 + rank] = g_candI[base + t];
    }
}

// ---------------- 5) topB2 (final rank) + keys/values/bias/temp, fused (validated R14) ----------------
__global__ void k_topB2prep(const float* __restrict__ beliefs,
                            const float* __restrict__ ge,
                            const float* __restrict__ gp,
                            const float* __restrict__ lt) {
    __shared__ __align__(16) float sv[512];
    __shared__ int topkS[32];
    __shared__ float gA[16][256];
    __shared__ float gpS[16];
    int t = threadIdx.x, w = t >> 5, lane = t & 31;

    if (t < 512) sv[t] = g_cand2V[t];
    if (t < 4)  g_temp[t] = fmaxf(expf(lt[t]), 0.1f);
    if (t < 16) gpS[t] = gp[t];
    __syncthreads();

    if (t < 512) {
        float v = sv[t];
        int rank = 0;
#pragma unroll 16
        for (int j4 = 0; j4 < 128; j4++) {
            float4 f = *reinterpret_cast<const float4*>(&sv[j4 * 4]);
            int j = j4 * 4;
            rank += (f.x > v) || (f.x == v && (j + 0) < t);
            rank += (f.y > v) || (f.y == v && (j + 1) < t);
            rank += (f.z > v) || (f.z == v && (j + 2) < t);
            rank += (f.w > v) || (f.w == v && (j + 3) < t);
        }
        if (rank < 32) topkS[rank] = g_cand2I[t];
    }
    __syncthreads();

    int idx = topkS[w];
    float v[8], kreg[8];
    float ss = 0.f;
#pragma unroll
    for (int j = 0; j < 8; j++) {
        v[j] = beliefs[(size_t)idx * 256 + j * 32 + lane];
        ss += v[j] * v[j];
    }
#pragma unroll
    for (int off = 16; off > 0; off >>= 1) ss += __shfl_xor_sync(0xffffffffu, ss, off);
    float inv = 1.0f / fmaxf(sqrtf(ss), 1e-8f);
#pragma unroll
    for (int j = 0; j < 8; j++) {
        kreg[j] = v[j] * inv;
        g_keys[w * 256 + j * 32 + lane] = kreg[j];
        g_vals[w * 256 + j * 32 + lane] = v[j];
    }
    if (w < 16) {
        float gv[8]; float gs = 0.f;
#pragma unroll
        for (int j = 0; j < 8; j++) {
            gv[j] = ge[w * 256 + j * 32 + lane];
            gs += gv[j] * gv[j];
        }
#pragma unroll
        for (int off = 16; off > 0; off >>= 1) gs += __shfl_xor_sync(0xffffffffu, gs, off);
        float gi = 1.0f / fmaxf(sqrtf(gs), 1e-8f);
#pragma unroll
        for (int j = 0; j < 8; j++) gA[w][j * 32 + lane] = gv[j] * gi;
    }
    __syncthreads();
    float best = -INFINITY;
#pragma unroll
    for (int g = 0; g < 16; g++) {
        float d = 0.f;
#pragma unroll
        for (int j = 0; j < 8; j++) d += kreg[j] * gA[g][j * 32 + lane];
#pragma unroll
        for (int off = 16; off > 0; off >>= 1) d += __shfl_xor_sync(0xffffffffu, d, off);
        best = fmaxf(best, d * gpS[g]);
    }
    if (lane == 0) g_bias[w] = best;
}

// ---------------- 6) W1T[nk][h], bf16 hi/lo ----------------
__global__ void __launch_bounds__(256) k_W1(const float* __restrict__ Wq) {
    __shared__ float keysS[32 * 256];
    __shared__ float aS[8 * 64];
    int t = threadIdx.x;
    int h0 = blockIdx.x * 64;
    int head = blockIdx.y;
#pragma unroll
    for (int i = 0; i < 32; i++) keysS[t + i * 256] = g_keys[t + i * 256];
    float acc[8];
#pragma unroll
    for (int j = 0; j < 8; j++) acc[j] = 0.f;
    int k4 = t >> 6, hl = t & 63;
    for (int dc = 0; dc < 32; dc++) {
        __syncthreads();
#pragma unroll
        for (int i = 0; i < 2; i++) {
            int e = t + i * 256;
            int dd = e >> 6, hh = e & 63;
            aS[dd * 64 + hh] = Wq[(size_t)(head * 256 + dc * 8 + dd) * 2048 + h0 + hh];
        }
        __syncthreads();
#pragma unroll
        for (int dd = 0; dd < 8; dd++) {
            float a = aS[dd * 64 + hl];
            int dg = dc * 8 + dd;
#pragma unroll
            for (int j = 0; j < 8; j++) acc[j] += a * keysS[(k4 * 8 + j) * 256 + dg];
        }
    }
    float scale = g_temp[head] * 0.0625f;
#pragma unroll
    for (int j = 0; j < 8; j++) {
        float v = acc[j] * scale;
        __nv_bfloat16 h, l;
        split_bf16(v, h, l);
        size_t o = (size_t)(head * 32 + k4 * 8 + j) * 2048 + h0 + hl;
        g_W1Thi[o] = h;
        g_W1Tlo[o] = l;
    }
}

// ---------------- 7) W2T swizzled-tile layout, bf16 hi/lo ----------------
// element (j, nk) -> tile(j>>7)*16384 + (j&127)*128 + (((nk>>3)^(j&7))<<3) + (nk&7)
__global__ void __launch_bounds__(128) k_W2(const float* __restrict__ Wo) {
    __shared__ float woS[1024];
    __shared__ float valT[256 * 33];
    int t = threadIdx.x;
    int j = blockIdx.x;
#pragma unroll
    for (int i = 0; i < 8; i++) woS[t + i * 128] = Wo[(size_t)j * 1024 + t + i * 128];
#pragma unroll
    for (int i = 0; i < 64; i++) {
        int e = t + i * 128;
        int k = e >> 8, d = e & 255;
        valT[d * 33 + k] = g_vals[e];
    }
    __syncthreads();
    int n = t >> 5, k = t & 31;
    float acc = 0.f;
#pragma unroll 8
    for (int d = 0; d < 256; d++) acc += valT[d * 33 + k] * woS[n * 256 + d];
    __nv_bfloat16 h, l;
    split_bf16(acc, h, l);
    int nk = t;
    int jl = j & 127;
    size_t off = (size_t)(j >> 7) * 16384 + jl * 128 + (((nk >> 3) ^ (jl & 7)) << 3) + (nk & 7);
    g_W2Thi[off] = h;
    g_W2Tlo[off] = l;
}

// ---------------- 8) FUSED: phase 1 verbatim R15; phase 2 via cp.async.bulk + mbarrier ----------------
// Phase-2 buffers: BUF_OFF + st*65536, each = hi plane 32KB | lo plane 32KB (swizzled, stride 128 halves)
static constexpr int ATTN_OFF  = 0;
static constexpr int PIPE_OFF  = 69632;
static constexpr int BUF_OFF   = 69632;
static constexpr int FUSED_SMEM = 208896;

__global__ void __launch_bounds__(256) k_fused(float* __restrict__ out) {
    extern __shared__ __align__(16) char smraw[];
    __shared__ __align__(8) unsigned long long s_mbar[2];
    __nv_bfloat16* attnS = reinterpret_cast<__nv_bfloat16*>(smraw + ATTN_OFF);
    __nv_bfloat16* sA = reinterpret_cast<__nv_bfloat16*>(smraw + PIPE_OFF);
    __nv_bfloat16* sB = sA + 20480;

    int t = threadIdx.x;
    int lane = t & 31, w = t >> 5;
    int wm = w & 3, wn = w >> 2;
    int m0 = blockIdx.x * 128;

    if (t == 0) {
        mbar_init(smem_u32(&s_mbar[0]), 1);
        mbar_init(smem_u32(&s_mbar[1]), 1);
    }
    // (first use is far after many __syncthreads in phase 1)

    float acc[2][8][4];
#pragma unroll
    for (int mt = 0; mt < 2; mt++)
#pragma unroll
        for (int nt = 0; nt < 8; nt++)
#pragma unroll
            for (int e = 0; e < 4; e++) acc[mt][nt][e] = 0.f;

    int lr = t >> 1;
    int s2 = (t & 1) * 2;

    // ---- Phase 1 prologue ----
#pragma unroll
    for (int c = 0; c < 2; c++) {
        int kc = c;
#pragma unroll
        for (int p = 0; p < 2; p++) {
            const __nv_bfloat16* gA = p ? g_hid_lo : g_hid_hi;
            const __nv_bfloat16* gB = p ? g_W1Tlo : g_W1Thi;
            __nv_bfloat16* dA = sA + (c * 2 + p) * 5120;
            __nv_bfloat16* dB = sB + (c * 2 + p) * 5120;
#pragma unroll
            for (int s = 0; s < 2; s++) {
                int seg = s2 + s;
                cp16(smem_u32(dA + lr * 40 + seg * 8), gA + (size_t)(m0 + lr) * 2048 + kc * 32 + seg * 8);
                cp16(smem_u32(dB + lr * 40 + seg * 8), gB + (size_t)lr * 2048 + kc * 32 + seg * 8);
            }
        }
        cp_commit();
    }

    int lrow = lane & 15;
    int lk   = (lane >> 4) << 3;

    // ---- Phase 1 mainloop (verbatim R15) ----
    for (int i = 0; i < 64; i++) {
        if (i < 63) asm volatile("cp.async.wait_group 1;");
        else        asm volatile("cp.async.wait_group 0;");
        __syncthreads();

        int st = i & 1;
        const __nv_bfloat16* Ah = sA + (st * 2 + 0) * 5120;
        const __nv_bfloat16* Al = sA + (st * 2 + 1) * 5120;
        const __nv_bfloat16* Bh = sB + (st * 2 + 0) * 5120;
        const __nv_bfloat16* Bl = sB + (st * 2 + 1) * 5120;

#pragma unroll
        for (int ks = 0; ks < 2; ks++) {
            int ko = ks * 16 + lk;
            unsigned ah[2][4], al[2][4], bb[4][4];
#pragma unroll
            for (int mt = 0; mt < 2; mt++)
                ldsm4(ah[mt], smem_u32(Ah + (wm * 32 + mt * 16 + lrow) * 40 + ko));
#pragma unroll
            for (int mt = 0; mt < 2; mt++)
                ldsm4(al[mt], smem_u32(Al + (wm * 32 + mt * 16 + lrow) * 40 + ko));
#pragma unroll
            for (int g = 0; g < 4; g++)
                ldsm4(bb[g], smem_u32(Bh + (wn * 64 + g * 16 + lrow) * 40 + ko));
#pragma unroll
            for (int mt = 0; mt < 2; mt++)
#pragma unroll
                for (int nt = 0; nt < 8; nt++)
                    mma16816(acc[mt][nt], ah[mt], bb[nt >> 1][nt & 1], bb[nt >> 1][(nt & 1) + 2]);
#pragma unroll
            for (int mt = 0; mt < 2; mt++)
#pragma unroll
                for (int nt = 0; nt < 8; nt++)
                    mma16816(acc[mt][nt], al[mt], bb[nt >> 1][nt & 1], bb[nt >> 1][(nt & 1) + 2]);
#pragma unroll
            for (int g = 0; g < 4; g++)
                ldsm4(bb[g], smem_u32(Bl + (wn * 64 + g * 16 + lrow) * 40 + ko));
#pragma unroll
            for (int mt = 0; mt < 2; mt++)
#pragma unroll
                for (int nt = 0; nt < 8; nt++)
                    mma16816(acc[mt][nt], ah[mt], bb[nt >> 1][nt & 1], bb[nt >> 1][(nt & 1) + 2]);
        }
        __syncthreads();

        if (i + 2 < 64) {
            int kc = i + 2;
#pragma unroll
            for (int p = 0; p < 2; p++) {
                const __nv_bfloat16* gA = p ? g_hid_lo : g_hid_hi;
                const __nv_bfloat16* gB = p ? g_W1Tlo : g_W1Thi;
                __nv_bfloat16* dA = sA + (st * 2 + p) * 5120;
                __nv_bfloat16* dB = sB + (st * 2 + p) * 5120;
#pragma unroll
                for (int s = 0; s < 2; s++) {
                    int seg = s2 + s;
                    cp16(smem_u32(dA + lr * 40 + seg * 8), gA + (size_t)(m0 + lr) * 2048 + kc * 32 + seg * 8);
                    cp16(smem_u32(dB + lr * 40 + seg * 8), gB + (size_t)lr * 2048 + kc * 32 + seg * 8);
                }
            }
            cp_commit();
        }
    }

    // ---- phase transition: pipe region free; kick off W2 tiles 0,1 via bulk copy ----
    if (t == 0) {
#pragma unroll
        for (int c = 0; c < 2; c++) {
            unsigned mb = smem_u32(&s_mbar[c]);
            unsigned dst = smem_u32(smraw + BUF_OFF + c * 65536);
            mbar_expect_tx(mb, 65536u);
            bulk_ld(dst,          g_W2Thi + (size_t)c * 16384, 32768u, mb);
            bulk_ld(dst + 32768u, g_W2Tlo + (size_t)c * 16384, 32768u, mb);
        }
    }

    // ---- softmax epilogue -> attn into SMEM (overlaps bulk loads) ----
    float bias8[4][2];
#pragma unroll
    for (int g = 0; g < 4; g++) {
        bias8[g][0] = g_bias[g * 8 + (lane & 3) * 2];
        bias8[g][1] = g_bias[g * 8 + (lane & 3) * 2 + 1];
    }

#pragma unroll
    for (int mt = 0; mt < 2; mt++) {
#pragma unroll
        for (int h2 = 0; h2 < 2; h2++) {
            int r = wm * 32 + mt * 16 + (lane >> 2) + h2 * 8;
#pragma unroll
            for (int hd = 0; hd < 2; hd++) {
                float s[8];
#pragma unroll
                for (int g = 0; g < 4; g++) {
                    int nt = hd * 4 + g;
                    s[g * 2]     = acc[mt][nt][h2 * 2]     + bias8[g][0];
                    s[g * 2 + 1] = acc[mt][nt][h2 * 2 + 1] + bias8[g][1];
                }
                float mx = s[0];
#pragma unroll
                for (int e = 1; e < 8; e++) mx = fmaxf(mx, s[e]);
                mx = fmaxf(mx, __shfl_xor_sync(0xffffffffu, mx, 1));
                mx = fmaxf(mx, __shfl_xor_sync(0xffffffffu, mx, 2));
                float ex[8], sum = 0.f;
#pragma unroll
                for (int e = 0; e < 8; e++) { ex[e] = __expf(s[e] - mx); sum += ex[e]; }
                sum += __shfl_xor_sync(0xffffffffu, sum, 1);
                sum += __shfl_xor_sync(0xffffffffu, sum, 2);
                float inv = 1.0f / sum;
#pragma unroll
                for (int g = 0; g < 4; g++) {
                    int col = wn * 64 + hd * 32 + g * 8 + (lane & 3) * 2;
                    float a0 = ex[g * 2] * inv, a1 = ex[g * 2 + 1] * inv;
                    __nv_bfloat16 h0b, l0b, h1b, l1b;
                    split_bf16(a0, h0b, l0b);
                    split_bf16(a1, h1b, l1b);
                    int o = r * 136 + col;
                    *reinterpret_cast<__nv_bfloat162*>(attnS + o)          = __nv_bfloat162(h0b, h1b);
                    *reinterpret_cast<__nv_bfloat162*>(attnS + 17408 + o)  = __nv_bfloat162(l0b, l1b);
                }
            }
        }
    }
    __syncthreads();   // attn visible to all warps

    // ---- Phase 2: 16 W2 n-tiles, bulk-loaded swizzled B (stride 128 halves) ----
    const __nv_bfloat16* Ah2 = attnS;
    const __nv_bfloat16* Al2 = attnS + 17408;

    for (int ni = 0; ni < 16; ni++) {
        int st = ni & 1;
        unsigned mb = smem_u32(&s_mbar[st]);
        mbar_wait(mb, (unsigned)((ni >> 1) & 1));

        const __nv_bfloat16* Bh = reinterpret_cast<const __nv_bfloat16*>(smraw + BUF_OFF + st * 65536);
        const __nv_bfloat16* Bl = Bh + 16384;
        int n0 = ni * 128;

        float acc2[2][8][4];
#pragma unroll
        for (int mt = 0; mt < 2; mt++)
#pragma unroll
            for (int nt = 0; nt < 8; nt++)
#pragma unroll
                for (int e = 0; e < 4; e++) acc2[mt][nt][e] = 0.f;

#pragma unroll
        for (int ks = 0; ks < 8; ks++) {
            int ko = ks * 16 + lk;         // multiple of 8
            unsigned ah[2][4], al[2][4], bb[4][4];
#pragma unroll
            for (int mt = 0; mt < 2; mt++)
                ldsm4(ah[mt], smem_u32(Ah2 + (wm * 32 + mt * 16 + lrow) * 136 + ko));
#pragma unroll
            for (int mt = 0; mt < 2; mt++)
                ldsm4(al[mt], smem_u32(Al2 + (wm * 32 + mt * 16 + lrow) * 136 + ko));
#pragma unroll
            for (int g = 0; g < 4; g++) {
                int row = wn * 64 + g * 16 + lrow;
                int ch  = (ko >> 3) ^ (row & 7);
                ldsm4(bb[g], smem_u32(Bh + row * 128 + ch * 8));
            }
#pragma unroll
            for (int mt = 0; mt < 2; mt++)
#pragma unroll
                for (int nt = 0; nt < 8; nt++)
                    mma16816(acc2[mt][nt], ah[mt], bb[nt >> 1][nt & 1], bb[nt >> 1][(nt & 1) + 2]);
#pragma unroll
            for (int mt = 0; mt < 2; mt++)
#pragma unroll
                for (int nt = 0; nt < 8; nt++)
                    mma16816(acc2[mt][nt], al[mt], bb[nt >> 1][nt & 1], bb[nt >> 1][(nt & 1) + 2]);
#pragma unroll
            for (int g = 0; g < 4; g++) {
                int row = wn * 64 + g * 16 + lrow;
                int ch  = (ko >> 3) ^ (row & 7);
                ldsm4(bb[g], smem_u32(Bl + row * 128 + ch * 8));
            }
#pragma unroll
            for (int mt = 0; mt < 2; mt++)
#pragma unroll
                for (int nt = 0; nt < 8; nt++)
                    mma16816(acc2[mt][nt], ah[mt], bb[nt >> 1][nt & 1], bb[nt >> 1][(nt & 1) + 2]);
        }
        __syncthreads();   // all threads done reading buffer st

        if (ni + 2 < 16 && t == 0) {
            int nc = ni + 2;
            unsigned dst = smem_u32(smraw + BUF_OFF + st * 65536);
            mbar_expect_tx(mb, 65536u);
            bulk_ld(dst,          g_W2Thi + (size_t)nc * 16384, 32768u, mb);
            bulk_ld(dst + 32768u, g_W2Tlo + (size_t)nc * 16384, 32768u, mb);
        }

        // store this n-tile
#pragma unroll
        for (int mt = 0; mt < 2; mt++) {
            int r0 = m0 + wm * 32 + mt * 16 + (lane >> 2);
#pragma unroll
            for (int nt = 0; nt < 8; nt++) {
                int col = n0 + wn * 64 + nt * 8 + (lane & 3) * 2;
                *reinterpret_cast<float2*>(&out[(size_t)r0 * 2048 + col]) =
                    make_float2(acc2[mt][nt][0], acc2[mt][nt][1]);
                *reinterpret_cast<float2*>(&out[(size_t)(r0 + 8) * 2048 + col]) =
                    make_float2(acc2[mt][nt][2], acc2[mt][nt][3]);
            }
        }
    }
}

// ---------------- launch ----------------
extern "C" void kernel_launch(void* const* d_in, const int* in_sizes, int n_in,
                              void* d_out, int out_size) {
    const float* hidden   = (const float*)d_in[0];
    const float* beliefs  = (const float*)d_in[1];
    const int*   mask     = (const int*)d_in[2];
    const float* goal_emb = (const float*)d_in[3];
    const float* goal_pri = (const float*)d_in[4];
    const float* Wq       = (const float*)d_in[5];
    const float* Wo       = (const float*)d_in[6];
    const float* log_temp = (const float*)d_in[7];
    float* out = (float*)d_out;

    cudaFuncSetAttribute(k_fused, cudaFuncAttributeMaxDynamicSharedMemorySize, FUSED_SMEM);

    k_convsum<<<dim3(64, 8), 256>>>(hidden);
    k_mean<<<8, 256>>>();
    k_q1024<<<128, 256>>>(Wq);
    k_rough<<<8192, 256>>>(beliefs, mask);
    k_topA<<<256, 256>>>();
    k_topB1<<<16, 512>>>();
    k_topB2prep<<<1, 1024>>>(beliefs, goal_emb, goal_pri, log_temp);
    k_W1<<<dim3(32, 4), 256>>>(Wq);
    k_W2<<<2048, 128>>>(Wo);
    k_fused<<<128, 256, FUSED_SMEM>>>(out);
}

// round 17
// speedup vs baseline: 1.3627x; 1.1078x over previous
#include <cuda_runtime.h>
#include <cuda_bf16.h>
#include <math.h>

// Problem dims
// B=4, T=4096 -> M=16384 rows; H=2048; D=256; NH=4; K=32; NB=65536; NG=16; NK=NH*K=128

// ---------------- device scratch (no allocations allowed) ----------------
__device__ float g_partial[64 * 2048];
__device__ float g_meanq[2048];
__device__ float g_q1024[1024];
__device__ float g_scores[65536];
__device__ float g_candV[8192];
__device__ int   g_candI[8192];
__device__ float g_cand2V[512];
__device__ int   g_cand2I[512];
__device__ float g_keys[32 * 256];
__device__ float g_vals[32 * 256];
__device__ float g_bias[32];
__device__ float g_temp[4];

// hidden planes, CHUNK-MAJOR swizzled: (m, h) -> (h>>5)*524288 + m*32 + rot16
// rot16: 16B chunk c=(h&31)>>3 stored at ((c + (m>>1)) & 3), byte b = h&7.
__device__ __nv_bfloat16 g_hid_hi[16384 * 2048];
__device__ __nv_bfloat16 g_hid_lo[16384 * 2048];
// W1 planes, chunk-major swizzled: (nk, h) -> (h>>5)*4096 + nk*32 + rot16(h&31, nk)
__device__ __nv_bfloat16 g_W1Thi[128 * 2048];
__device__ __nv_bfloat16 g_W1Tlo[128 * 2048];
// W2 planes (validated R16): (j, nk) -> (j>>7)*16384 + (j&127)*128 + (((nk>>3)^(j&7))<<3) + (nk&7)
__device__ __nv_bfloat16 g_W2Thi[2048 * 128];
__device__ __nv_bfloat16 g_W2Tlo[2048 * 128];

// ---------------- PTX helpers ----------------
__device__ __forceinline__ unsigned smem_u32(const void* p) {
    return (unsigned)__cvta_generic_to_shared(p);
}
__device__ __forceinline__ void ldsm4(unsigned* r, unsigned addr) {
    asm volatile("ldmatrix.sync.aligned.m8n8.x4.shared.b16 {%0,%1,%2,%3}, [%4];"
        : "=r"(r[0]), "=r"(r[1]), "=r"(r[2]), "=r"(r[3]) : "r"(addr));
}
// b0 = k[0:8] half, b1 = k[8:16] half of the SAME n8 subtile (non-contiguous regs)
__device__ __forceinline__ void mma16816(float* c, const unsigned* a, unsigned b0, unsigned b1) {
    asm volatile("mma.sync.aligned.m16n8k16.row.col.f32.bf16.bf16.f32 "
        "{%0,%1,%2,%3}, {%4,%5,%6,%7}, {%8,%9}, {%0,%1,%2,%3};"
        : "+f"(c[0]), "+f"(c[1]), "+f"(c[2]), "+f"(c[3])
        : "r"(a[0]), "r"(a[1]), "r"(a[2]), "r"(a[3]), "r"(b0), "r"(b1));
}
__device__ __forceinline__ void split_bf16(float x, __nv_bfloat16& h, __nv_bfloat16& l) {
    h = __float2bfloat16(x);
    l = __float2bfloat16(x - __bfloat162float(h));
}
__device__ __forceinline__ void mbar_init(unsigned addr, unsigned cnt) {
    asm volatile("mbarrier.init.shared.b64 [%0], %1;" :: "r"(addr), "r"(cnt) : "memory");
}
__device__ __forceinline__ void mbar_expect_tx(unsigned addr, unsigned bytes) {
    asm volatile("mbarrier.arrive.expect_tx.shared.b64 _, [%0], %1;" :: "r"(addr), "r"(bytes) : "memory");
}
__device__ __forceinline__ void bulk_ld(unsigned dst, const void* src, unsigned bytes, unsigned mbar) {
    asm volatile("cp.async.bulk.shared::cta.global.mbarrier::complete_tx::bytes [%0], [%1], %2, [%3];"
        :: "r"(dst), "l"(src), "r"(bytes), "r"(mbar) : "memory");
}
__device__ __forceinline__ void mbar_wait(unsigned addr, unsigned parity) {
    asm volatile(
        "{\n\t.reg .pred P;\n\t"
        "MBWAIT_%=:\n\t"
        "mbarrier.try_wait.parity.acquire.cta.shared::cta.b64 P, [%0], %1;\n\t"
        "@!P bra MBWAIT_%=;\n\t"
        "}" :: "r"(addr), "r"(parity) : "memory");
}

// ---------------- 1) column sums + hi/lo split, chunk-major swizzled layout ----------------
__global__ void k_convsum(const float* __restrict__ hidden) {
    int col = blockIdx.y * 256 + threadIdx.x;
    int r0  = blockIdx.x * 256;
    int kc = col >> 5, c5 = col & 31;
    int cb = c5 >> 3, bb = c5 & 7;
    size_t base = (size_t)kc * 524288;
    float s = 0.f;
#pragma unroll 4
    for (int r = 0; r < 256; r++) {
        int m = r0 + r;
        float x = hidden[(size_t)m * 2048 + col];
        s += x;
        __nv_bfloat16 h, l;
        split_bf16(x, h, l);
        size_t off = base + (size_t)m * 32 + (((cb + (m >> 1)) & 3) << 3) + bb;
        g_hid_hi[off] = h;
        g_hid_lo[off] = l;
    }
    g_partial[blockIdx.x * 2048 + col] = s;
}

__global__ void k_mean() {
    int col = blockIdx.x * 256 + threadIdx.x;
    float s = 0.f;
#pragma unroll
    for (int r = 0; r < 64; r++) s += g_partial[r * 2048 + col];
    g_meanq[col] = s * (1.0f / 16384.0f);
}

// ---------------- 2) q1024 = Wq @ mean_query ----------------
__global__ void k_q1024(const float* __restrict__ Wq) {
    int row  = (blockIdx.x << 3) + (threadIdx.x >> 5);
    int lane = threadIdx.x & 31;
    const float* wp = Wq + (size_t)row * 2048;
    float s = 0.f;
#pragma unroll 8
    for (int j = 0; j < 64; j++) s += wp[j * 32 + lane] * g_meanq[j * 32 + lane];
#pragma unroll
    for (int off = 16; off > 0; off >>= 1) s += __shfl_xor_sync(0xffffffffu, s, off);
    if (lane == 0) g_q1024[row] = s;
}

// ---------------- 3) rough scores ----------------
__global__ void k_rough(const float* __restrict__ beliefs, const int* __restrict__ mask) {
    __shared__ float rqS[256];
    int t = threadIdx.x;
    rqS[t] = 0.25f * (g_q1024[t] + g_q1024[256 + t] + g_q1024[512 + t] + g_q1024[768 + t]);
    __syncthreads();
    int w    = (blockIdx.x << 3) + (t >> 5);
    int lane = t & 31;
    const float* bp = beliefs + (size_t)w * 256;
    float dot = 0.f, ss = 0.f;
#pragma unroll
    for (int j = 0; j < 8; j++) {
        float v = bp[j * 32 + lane];
        dot += v * rqS[j * 32 + lane];
        ss  += v * v;
    }
#pragma unroll
    for (int off = 16; off > 0; off >>= 1) {
        dot += __shfl_xor_sync(0xffffffffu, dot, off);
        ss  += __shfl_xor_sync(0xffffffffu, ss, off);
    }
    if (lane == 0) {
        float score = dot / fmaxf(sqrtf(ss), 1e-8f);
        g_scores[w] = (mask[w] != 0) ? score : -1e30f;
    }
}

// ---------------- 4) top-32 via HIERARCHICAL rank counting ----------------
__global__ void k_topA() {
    __shared__ __align__(16) float sv[256];
    int t = threadIdx.x;
    float v = g_scores[blockIdx.x * 256 + t];
    sv[t] = v;
    __syncthreads();
    int rank = 0;
#pragma unroll 16
    for (int j4 = 0; j4 < 64; j4++) {
        float4 f = *reinterpret_cast<const float4*>(&sv[j4 * 4]);
        int j = j4 * 4;
        rank += (f.x > v) || (f.x == v && (j + 0) < t);
        rank += (f.y > v) || (f.y == v && (j + 1) < t);
        rank += (f.z > v) || (f.z == v && (j + 2) < t);
        rank += (f.w > v) || (f.w == v && (j + 3) < t);
    }
    if (rank < 32) {
        g_candV[blockIdx.x * 32 + rank] = v;
        g_candI[blockIdx.x * 32 + rank] = blockIdx.x * 256 + t;
    }
}

__global__ void k_topB1() {
    __shared__ __align__(16) float sv[512];
    int t = threadIdx.x;
    int base = blockIdx.x * 512;
    float v = g_candV[base + t];
    sv[t] = v;
    __syncthreads();
    int rank = 0;
#pragma unroll 16
    for (int j4 = 0; j4 < 128; j4++) {
        float4 f = *reinterpret_cast<const float4*>(&sv[j4 * 4]);
        int j = j4 * 4;
        rank += (f.x > v) || (f.x == v && (j + 0) < t);
        rank += (f.y > v) || (f.y == v && (j + 1) < t);
        rank += (f.z > v) || (f.z == v && (j + 2) < t);
        rank += (f.w > v) || (f.w == v && (j + 3) < t);
    }
    if (rank < 32) {
        g_cand2V[blockIdx.x * 32 + rank] = v;
        g_cand2I[blockIdx.x * 32 + rank] = g_candI[base + t];
    }
}

// ---------------- 5) topB2 + keys/values/bias/temp (validated) ----------------
__global__ void k_topB2prep(const float* __restrict__ beliefs,
                            const float* __restrict__ ge,
                            const float* __restrict__ gp,
                            const float* __restrict__ lt) {
    __shared__ __align__(16) float sv[512];
    __shared__ int topkS[32];
    __shared__ float gA[16][256];
    __shared__ float gpS[16];
    int t = threadIdx.x, w = t >> 5, lane = t & 31;

    if (t < 512) sv[t] = g_cand2V[t];
    if (t < 4)  g_temp[t] = fmaxf(expf(lt[t]), 0.1f);
    if (t < 16) gpS[t] = gp[t];
    __syncthreads();

    if (t < 512) {
        float v = sv[t];
        int rank = 0;
#pragma unroll 16
        for (int j4 = 0; j4 < 128; j4++) {
            float4 f = *reinterpret_cast<const float4*>(&sv[j4 * 4]);
            int j = j4 * 4;
            rank += (f.x > v) || (f.x == v && (j + 0) < t);
            rank += (f.y > v) || (f.y == v && (j + 1) < t);
            rank += (f.z > v) || (f.z == v && (j + 2) < t);
            rank += (f.w > v) || (f.w == v && (j + 3) < t);
        }
        if (rank < 32) topkS[rank] = g_cand2I[t];
    }
    __syncthreads();

    int idx = topkS[w];
    float v[8], kreg[8];
    float ss = 0.f;
#pragma unroll
    for (int j = 0; j < 8; j++) {
        v[j] = beliefs[(size_t)idx * 256 + j * 32 + lane];
        ss += v[j] * v[j];
    }
#pragma unroll
    for (int off = 16; off > 0; off >>= 1) ss += __shfl_xor_sync(0xffffffffu, ss, off);
    float inv = 1.0f / fmaxf(sqrtf(ss), 1e-8f);
#pragma unroll
    for (int j = 0; j < 8; j++) {
        kreg[j] = v[j] * inv;
        g_keys[w * 256 + j * 32 + lane] = kreg[j];
        g_vals[w * 256 + j * 32 + lane] = v[j];
    }
    if (w < 16) {
        float gv[8]; float gs = 0.f;
#pragma unroll
        for (int j = 0; j < 8; j++) {
            gv[j] = ge[w * 256 + j * 32 + lane];
            gs += gv[j] * gv[j];
        }
#pragma unroll
        for (int off = 16; off > 0; off >>= 1) gs += __shfl_xor_sync(0xffffffffu, gs, off);
        float gi = 1.0f / fmaxf(sqrtf(gs), 1e-8f);
#pragma unroll
        for (int j = 0; j < 8; j++) gA[w][j * 32 + lane] = gv[j] * gi;
    }
    __syncthreads();
    float best = -INFINITY;
#pragma unroll
    for (int g = 0; g < 16; g++) {
        float d = 0.f;
#pragma unroll
        for (int j = 0; j < 8; j++) d += kreg[j] * gA[g][j * 32 + lane];
#pragma unroll
        for (int off = 16; off > 0; off >>= 1) d += __shfl_xor_sync(0xffffffffu, d, off);
        best = fmaxf(best, d * gpS[g]);
    }
    if (lane == 0) g_bias[w] = best;
}

// ---------------- 6) W1T chunk-major swizzled, bf16 hi/lo ----------------
__global__ void __launch_bounds__(256) k_W1(const float* __restrict__ Wq) {
    __shared__ float keysS[32 * 256];
    __shared__ float aS[8 * 64];
    int t = threadIdx.x;
    int h0 = blockIdx.x * 64;
    int head = blockIdx.y;
#pragma unroll
    for (int i = 0; i < 32; i++) keysS[t + i * 256] = g_keys[t + i * 256];
    float acc[8];
#pragma unroll
    for (int j = 0; j < 8; j++) acc[j] = 0.f;
    int k4 = t >> 6, hl = t & 63;
    for (int dc = 0; dc < 32; dc++) {
        __syncthreads();
#pragma unroll
        for (int i = 0; i < 2; i++) {
            int e = t + i * 256;
            int dd = e >> 6, hh = e & 63;
            aS[dd * 64 + hh] = Wq[(size_t)(head * 256 + dc * 8 + dd) * 2048 + h0 + hh];
        }
        __syncthreads();
#pragma unroll
        for (int dd = 0; dd < 8; dd++) {
            float a = aS[dd * 64 + hl];
            int dg = dc * 8 + dd;
#pragma unroll
            for (int j = 0; j < 8; j++) acc[j] += a * keysS[(k4 * 8 + j) * 256 + dg];
        }
    }
    float scale = g_temp[head] * 0.0625f;
    int h = h0 + hl;
    int kc = h >> 5, c5 = h & 31;
#pragma unroll
    for (int j = 0; j < 8; j++) {
        float v = acc[j] * scale;
        __nv_bfloat16 hh, ll;
        split_bf16(v, hh, ll);
        int nk = head * 32 + k4 * 8 + j;
        size_t o = (size_t)kc * 4096 + (size_t)nk * 32 + ((((c5 >> 3) + (nk >> 1)) & 3) << 3) + (c5 & 7);
        g_W1Thi[o] = hh;
        g_W1Tlo[o] = ll;
    }
}

// ---------------- 7) W2T swizzled-tile layout (validated R16) ----------------
__global__ void __launch_bounds__(128) k_W2(const float* __restrict__ Wo) {
    __shared__ float woS[1024];
    __shared__ float valT[256 * 33];
    int t = threadIdx.x;
    int j = blockIdx.x;
#pragma unroll
    for (int i = 0; i < 8; i++) woS[t + i * 128] = Wo[(size_t)j * 1024 + t + i * 128];
#pragma unroll
    for (int i = 0; i < 64; i++) {
        int e = t + i * 128;
        int k = e >> 8, d = e & 255;
        valT[d * 33 + k] = g_vals[e];
    }
    __syncthreads();
    int n = t >> 5, k = t & 31;
    float acc = 0.f;
#pragma unroll 8
    for (int d = 0; d < 256; d++) acc += valT[d * 33 + k] * woS[n * 256 + d];
    __nv_bfloat16 h, l;
    split_bf16(acc, h, l);
    int nk = t;
    int jl = j & 127;
    size_t off = (size_t)(j >> 7) * 16384 + jl * 128 + (((nk >> 3) ^ (jl & 7)) << 3) + (nk & 7);
    g_W2Thi[off] = h;
    g_W2Tlo[off] = l;
}

// ---------------- 8) FUSED: both phases via cp.async.bulk + mbarrier ----------------
// Phase-1 stage st at PIPE_OFF + st*32768: Ahi 8K | Alo 8K | Bhi 8K | Blo 8K (32-half rows, rot16)
// Phase-2 buffers at BUF_OFF + st*65536 (validated R16).
static constexpr int ATTN_OFF  = 0;
static constexpr int PIPE_OFF  = 69632;
static constexpr int BUF_OFF   = 69632;
static constexpr int FUSED_SMEM = 208896;

__global__ void __launch_bounds__(256) k_fused(float* __restrict__ out) {
    extern __shared__ __align__(16) char smraw[];
    __shared__ __align__(8) unsigned long long s_mbar[4];   // 0,1 = phase1; 2,3 = phase2
    __nv_bfloat16* attnS = reinterpret_cast<__nv_bfloat16*>(smraw + ATTN_OFF);

    int t = threadIdx.x;
    int lane = t & 31, w = t >> 5;
    int wm = w & 3, wn = w >> 2;
    int m0 = blockIdx.x * 128;

    if (t == 0) {
#pragma unroll
        for (int i = 0; i < 4; i++) mbar_init(smem_u32(&s_mbar[i]), 1);
    }
    __syncthreads();

    float acc[2][8][4];
#pragma unroll
    for (int mt = 0; mt < 2; mt++)
#pragma unroll
        for (int nt = 0; nt < 8; nt++)
#pragma unroll
            for (int e = 0; e < 4; e++) acc[mt][nt][e] = 0.f;

    auto load_p1 = [&](int kc, int st) {
        unsigned mb  = smem_u32(&s_mbar[st]);
        unsigned dst = smem_u32(smraw + PIPE_OFF + st * 32768);
        mbar_expect_tx(mb, 32768u);
        bulk_ld(dst,          g_hid_hi + (size_t)kc * 524288 + (size_t)m0 * 32, 8192u, mb);
        bulk_ld(dst + 8192u,  g_hid_lo + (size_t)kc * 524288 + (size_t)m0 * 32, 8192u, mb);
        bulk_ld(dst + 16384u, g_W1Thi + (size_t)kc * 4096, 8192u, mb);
        bulk_ld(dst + 24576u, g_W1Tlo + (size_t)kc * 4096, 8192u, mb);
    };

    if (t == 0) {
        load_p1(0, 0);
        load_p1(1, 1);
    }

    int lrow = lane & 15;
    int lk   = (lane >> 4) << 3;

    // ---- Phase 1 mainloop: 2 stages, mbar parity (i>>1)&1 (validated pattern) ----
    for (int i = 0; i < 64; i++) {
        int st = i & 1;
        mbar_wait(smem_u32(&s_mbar[st]), (unsigned)((i >> 1) & 1));

        const __nv_bfloat16* base = reinterpret_cast<const __nv_bfloat16*>(smraw + PIPE_OFF + st * 32768);
        const __nv_bfloat16* Ah = base;
        const __nv_bfloat16* Al = base + 4096;
        const __nv_bfloat16* Bh = base + 8192;
        const __nv_bfloat16* Bl = base + 12288;

#pragma unroll
        for (int ks = 0; ks < 2; ks++) {
            int ko = ks * 16 + lk;
            int cl = ko >> 3;
            unsigned ah[2][4], al[2][4], bb[4][4];
#pragma unroll
            for (int mt = 0; mt < 2; mt++) {
                int row = wm * 32 + mt * 16 + lrow;
                int ch = (cl + (row >> 1)) & 3;
                ldsm4(ah[mt], smem_u32(Ah + row * 32 + ch * 8));
            }
#pragma unroll
            for (int mt = 0; mt < 2; mt++) {
                int row = wm * 32 + mt * 16 + lrow;
                int ch = (cl + (row >> 1)) & 3;
                ldsm4(al[mt], smem_u32(Al + row * 32 + ch * 8));
            }
#pragma unroll
            for (int g = 0; g < 4; g++) {
                int row = wn * 64 + g * 16 + lrow;
                int ch = (cl + (row >> 1)) & 3;
                ldsm4(bb[g], smem_u32(Bh + row * 32 + ch * 8));
            }
#pragma unroll
            for (int mt = 0; mt < 2; mt++)
#pragma unroll
                for (int nt = 0; nt < 8; nt++)
                    mma16816(acc[mt][nt], ah[mt], bb[nt >> 1][nt & 1], bb[nt >> 1][(nt & 1) + 2]);
#pragma unroll
            for (int mt = 0; mt < 2; mt++)
#pragma unroll
                for (int nt = 0; nt < 8; nt++)
                    mma16816(acc[mt][nt], al[mt], bb[nt >> 1][nt & 1], bb[nt >> 1][(nt & 1) + 2]);
#pragma unroll
            for (int g = 0; g < 4; g++) {
                int row = wn * 64 + g * 16 + lrow;
                int ch = (cl + (row >> 1)) & 3;
                ldsm4(bb[g], smem_u32(Bl + row * 32 + ch * 8));
            }
#pragma unroll
            for (int mt = 0; mt < 2; mt++)
#pragma unroll
                for (int nt = 0; nt < 8; nt++)
                    mma16816(acc[mt][nt], ah[mt], bb[nt >> 1][nt & 1], bb[nt >> 1][(nt & 1) + 2]);
        }
        __syncthreads();

        if (i + 2 < 64 && t == 0) load_p1(i + 2, st);
    }

    // ---- transition: kick W2 tiles 0,1 (mbar 2,3) ----
    if (t == 0) {
#pragma unroll
        for (int c = 0; c < 2; c++) {
            unsigned mb = smem_u32(&s_mbar[2 + c]);
            unsigned dst = smem_u32(smraw + BUF_OFF + c * 65536);
            mbar_expect_tx(mb, 65536u);
            bulk_ld(dst,          g_W2Thi + (size_t)c * 16384, 32768u, mb);
            bulk_ld(dst + 32768u, g_W2Tlo + (size_t)c * 16384, 32768u, mb);
        }
    }

    // ---- softmax epilogue -> attn into SMEM ----
    float bias8[4][2];
#pragma unroll
    for (int g = 0; g < 4; g++) {
        bias8[g][0] = g_bias[g * 8 + (lane & 3) * 2];
        bias8[g][1] = g_bias[g * 8 + (lane & 3) * 2 + 1];
    }

#pragma unroll
    for (int mt = 0; mt < 2; mt++) {
#pragma unroll
        for (int h2 = 0; h2 < 2; h2++) {
            int r = wm * 32 + mt * 16 + (lane >> 2) + h2 * 8;
#pragma unroll
            for (int hd = 0; hd < 2; hd++) {
                float s[8];
#pragma unroll
                for (int g = 0; g < 4; g++) {
                    int nt = hd * 4 + g;
                    s[g * 2]     = acc[mt][nt][h2 * 2]     + bias8[g][0];
                    s[g * 2 + 1] = acc[mt][nt][h2 * 2 + 1] + bias8[g][1];
                }
                float mx = s[0];
#pragma unroll
                for (int e = 1; e < 8; e++) mx = fmaxf(mx, s[e]);
                mx = fmaxf(mx, __shfl_xor_sync(0xffffffffu, mx, 1));
                mx = fmaxf(mx, __shfl_xor_sync(0xffffffffu, mx, 2));
                float ex[8], sum = 0.f;
#pragma unroll
                for (int e = 0; e < 8; e++) { ex[e] = __expf(s[e] - mx); sum += ex[e]; }
                sum += __shfl_xor_sync(0xffffffffu, sum, 1);
                sum += __shfl_xor_sync(0xffffffffu, sum, 2);
                float inv = 1.0f / sum;
#pragma unroll
                for (int g = 0; g < 4; g++) {
                    int col = wn * 64 + hd * 32 + g * 8 + (lane & 3) * 2;
                    float a0 = ex[g * 2] * inv, a1 = ex[g * 2 + 1] * inv;
                    __nv_bfloat16 h0b, l0b, h1b, l1b;
                    split_bf16(a0, h0b, l0b);
                    split_bf16(a1, h1b, l1b);
                    int o = r * 136 + col;
                    *reinterpret_cast<__nv_bfloat162*>(attnS + o)          = __nv_bfloat162(h0b, h1b);
                    *reinterpret_cast<__nv_bfloat162*>(attnS + 17408 + o)  = __nv_bfloat162(l0b, l1b);
                }
            }
        }
    }
    __syncthreads();

    // ---- Phase 2 (validated R16) ----
    const __nv_bfloat16* Ah2 = attnS;
    const __nv_bfloat16* Al2 = attnS + 17408;

    for (int ni = 0; ni < 16; ni++) {
        int st = ni & 1;
        unsigned mb = smem_u32(&s_mbar[2 + st]);
        mbar_wait(mb, (unsigned)((ni >> 1) & 1));

        const __nv_bfloat16* Bh = reinterpret_cast<const __nv_bfloat16*>(smraw + BUF_OFF + st * 65536);
        const __nv_bfloat16* Bl = Bh + 16384;
        int n0 = ni * 128;

        float acc2[2][8][4];
#pragma unroll
        for (int mt = 0; mt < 2; mt++)
#pragma unroll
            for (int nt = 0; nt < 8; nt++)
#pragma unroll
                for (int e = 0; e < 4; e++) acc2[mt][nt][e] = 0.f;

#pragma unroll
        for (int ks = 0; ks < 8; ks++) {
            int ko = ks * 16 + lk;
            unsigned ah[2][4], al[2][4], bb[4][4];
#pragma unroll
            for (int mt = 0; mt < 2; mt++)
                ldsm4(ah[mt], smem_u32(Ah2 + (wm * 32 + mt * 16 + lrow) * 136 + ko));
#pragma unroll
            for (int mt = 0; mt < 2; mt++)
                ldsm4(al[mt], smem_u32(Al2 + (wm * 32 + mt * 16 + lrow) * 136 + ko));
#pragma unroll
            for (int g = 0; g < 4; g++) {
                int row = wn * 64 + g * 16 + lrow;
                int ch  = (ko >> 3) ^ (row & 7);
                ldsm4(bb[g], smem_u32(Bh + row * 128 + ch * 8));
            }
#pragma unroll
            for (int mt = 0; mt < 2; mt++)
#pragma unroll
                for (int nt = 0; nt < 8; nt++)
                    mma16816(acc2[mt][nt], ah[mt], bb[nt >> 1][nt & 1], bb[nt >> 1][(nt & 1) + 2]);
#pragma unroll
            for (int mt = 0; mt < 2; mt++)
#pragma unroll
                for (int nt = 0; nt < 8; nt++)
                    mma16816(acc2[mt][nt], al[mt], bb[nt >> 1][nt & 1], bb[nt >> 1][(nt & 1) + 2]);
#pragma unroll
            for (int g = 0; g < 4; g++) {
                int row = wn * 64 + g * 16 + lrow;
                int ch  = (ko >> 3) ^ (row & 7);
                ldsm4(bb[g], smem_u32(Bl + row * 128 + ch * 8));
            }
#pragma unroll
            for (int mt = 0; mt < 2; mt++)
#pragma unroll
                for (int nt = 0; nt < 8; nt++)
                    mma16816(acc2[mt][nt], ah[mt], bb[nt >> 1][nt & 1], bb[nt >> 1][(nt & 1) + 2]);
        }
        __syncthreads();

        if (ni + 2 < 16 && t == 0) {
            int nc = ni + 2;
            unsigned dst = smem_u32(smraw + BUF_OFF + st * 65536);
            mbar_expect_tx(mb, 65536u);
            bulk_ld(dst,          g_W2Thi + (size_t)nc * 16384, 32768u, mb);
            bulk_ld(dst + 32768u, g_W2Tlo + (size_t)nc * 16384, 32768u, mb);
        }

        // store this n-tile
#pragma unroll
        for (int mt = 0; mt < 2; mt++) {
            int r0 = m0 + wm * 32 + mt * 16 + (lane >> 2);
#pragma unroll
            for (int nt = 0; nt < 8; nt++) {
                int col = n0 + wn * 64 + nt * 8 + (lane & 3) * 2;
                *reinterpret_cast<float2*>(&out[(size_t)r0 * 2048 + col]) =
                    make_float2(acc2[mt][nt][0], acc2[mt][nt][1]);
                *reinterpret_cast<float2*>(&out[(size_t)(r0 + 8) * 2048 + col]) =
                    make_float2(acc2[mt][nt][2], acc2[mt][nt][3]);
            }
        }
    }
}

// ---------------- launch ----------------
extern "C" void kernel_launch(void* const* d_in, const int* in_sizes, int n_in,
                              void* d_out, int out_size) {
    const float* hidden   = (const float*)d_in[0];
    const float* beliefs  = (const float*)d_in[1];
    const int*   mask     = (const int*)d_in[2];
    const float* goal_emb = (const float*)d_in[3];
    const float* goal_pri = (const float*)d_in[4];
    const float* Wq       = (const float*)d_in[5];
    const float* Wo       = (const float*)d_in[6];
    const float* log_temp = (const float*)d_in[7];
    float* out = (float*)d_out;

    cudaFuncSetAttribute(k_fused, cudaFuncAttributeMaxDynamicSharedMemorySize, FUSED_SMEM);

    k_convsum<<<dim3(64, 8), 256>>>(hidden);
    k_mean<<<8, 256>>>();
    k_q1024<<<128, 256>>>(Wq);
    k_rough<<<8192, 256>>>(beliefs, mask);
    k_topA<<<256, 256>>>();
    k_topB1<<<16, 512>>>();
    k_topB2prep<<<1, 1024>>>(beliefs, goal_emb, goal_pri, log_temp);
    k_W1<<<dim3(32, 4), 256>>>(Wq);
    k_W2<<<2048, 128>>>(Wo);
    k_fused<<<128, 256, FUSED_SMEM>>>(out);
}